// round 2
// baseline (speedup 1.0000x reference)
#include <cuda_runtime.h>
#include <cuda_bf16.h>
#include <cstdint>

// Problem dims (fixed by the dataset)
#define Bb   128
#define Tt   1024
#define Dd   256
#define Hh   256
#define BT   (Bb * Tt)   // 131072

// Scratch for precomputed input projections (x@W + b), ~134MB each.
__device__ float g_xz[(size_t)BT * Hh];
__device__ float g_xr[(size_t)BT * Hh];
__device__ float g_xh[(size_t)BT * Hh];

// Packed dual-FP32 FMA (Blackwell FFMA2): d = a*b + c on both lanes.
__device__ __forceinline__ float2 ffma2(float2 a, float2 b, float2 c) {
    float2 d;
    asm("fma.rn.f32x2 %0, %1, %2, %3;"
        : "=l"(*reinterpret_cast<unsigned long long*>(&d))
        : "l"(*reinterpret_cast<const unsigned long long*>(&a)),
          "l"(*reinterpret_cast<const unsigned long long*>(&b)),
          "l"(*reinterpret_cast<const unsigned long long*>(&c)));
    return d;
}

__device__ __forceinline__ float hsig(float x) {
    return fminf(fmaxf(fmaf(x, 0.2f, 0.5f), 0.0f), 1.0f);
}

// ---------------------------------------------------------------------------
// Projection GEMM: out[r, c] = sum_k x[r,k] * W[k,c] + bias[c]
// grid = (BT/64, H/128, 3), block = 256.
// Tile 64 rows x 128 cols, k-chunks of 16. Each thread: 4 rows x 8 cols.
// ---------------------------------------------------------------------------
__global__ __launch_bounds__(256) void proj_kernel(
    const float* __restrict__ x,
    const float* __restrict__ Wz, const float* __restrict__ Wr, const float* __restrict__ Wh,
    const float* __restrict__ bz, const float* __restrict__ br, const float* __restrict__ bh)
{
    const float* W; const float* bias; float* out;
    if (blockIdx.z == 0)      { W = Wz; bias = bz; out = g_xz; }
    else if (blockIdx.z == 1) { W = Wr; bias = br; out = g_xr; }
    else                      { W = Wh; bias = bh; out = g_xh; }

    const int row0 = blockIdx.x * 64;
    const int col0 = blockIdx.y * 128;
    const int tid  = threadIdx.x;

    __shared__ float As[16][65];    // [k][row]
    __shared__ float Bs[16][128];   // [k][col]

    const int trow = tid >> 4;      // 0..15
    const int tcol = tid & 15;      // 0..15
    const int r0   = trow * 4;
    const int c0   = tcol * 8;

    // bias preload (same for all rows)
    float2 bv[4];
#pragma unroll
    for (int j = 0; j < 4; j++)
        bv[j] = *reinterpret_cast<const float2*>(&bias[col0 + c0 + 2 * j]);

    float2 acc[4][4];
#pragma unroll
    for (int i = 0; i < 4; i++)
#pragma unroll
        for (int j = 0; j < 4; j++) acc[i][j] = bv[j];

    const int ar = tid >> 2;            // 0..63 (A row within tile)
    const int ak = (tid & 3) * 4;       // 0,4,8,12
    const int bk = tid >> 4;            // 0..15 (B k within chunk)
    const int bc = (tid & 15) * 8;      // col within tile

    for (int kc = 0; kc < Dd; kc += 16) {
        // load A chunk (64 x 16) transposed into As[k][row]
        float4 av = *reinterpret_cast<const float4*>(
            &x[(size_t)(row0 + ar) * Dd + kc + ak]);
        As[ak + 0][ar] = av.x;
        As[ak + 1][ar] = av.y;
        As[ak + 2][ar] = av.z;
        As[ak + 3][ar] = av.w;

        // load B chunk (16 x 128)
        const float4* src = reinterpret_cast<const float4*>(
            &W[(size_t)(kc + bk) * Hh + col0 + bc]);
        *reinterpret_cast<float4*>(&Bs[bk][bc])     = src[0];
        *reinterpret_cast<float4*>(&Bs[bk][bc + 4]) = src[1];

        __syncthreads();

#pragma unroll
        for (int kk = 0; kk < 16; kk++) {
            float2 b0 = *reinterpret_cast<const float2*>(&Bs[kk][c0 + 0]);
            float2 b1 = *reinterpret_cast<const float2*>(&Bs[kk][c0 + 2]);
            float2 b2 = *reinterpret_cast<const float2*>(&Bs[kk][c0 + 4]);
            float2 b3 = *reinterpret_cast<const float2*>(&Bs[kk][c0 + 6]);
#pragma unroll
            for (int i = 0; i < 4; i++) {
                float a = As[kk][r0 + i];
                float2 a2 = make_float2(a, a);
                acc[i][0] = ffma2(b0, a2, acc[i][0]);
                acc[i][1] = ffma2(b1, a2, acc[i][1]);
                acc[i][2] = ffma2(b2, a2, acc[i][2]);
                acc[i][3] = ffma2(b3, a2, acc[i][3]);
            }
        }
        __syncthreads();
    }

#pragma unroll
    for (int i = 0; i < 4; i++) {
        float4 v0 = make_float4(acc[i][0].x, acc[i][0].y, acc[i][1].x, acc[i][1].y);
        float4 v1 = make_float4(acc[i][2].x, acc[i][2].y, acc[i][3].x, acc[i][3].y);
        float* dst = &out[(size_t)(row0 + r0 + i) * Hh + col0 + c0];
        *reinterpret_cast<float4*>(dst)     = v0;
        *reinterpret_cast<float4*>(dst + 4) = v1;
    }
}

// ---------------------------------------------------------------------------
// Recurrent scan: grid = 32 CTAs, block = 256 threads.
// Each CTA owns 4 batch elements (bb = tid>>6), each thread owns 4 output
// columns (c0 = (tid&63)*4) of one batch element. h lives in SMEM (for the
// k-broadcast) + registers (own 4 elements). No inter-CTA communication.
// ---------------------------------------------------------------------------
__global__ __launch_bounds__(256) void scan_kernel(
    const float* __restrict__ Uz, const float* __restrict__ Ur,
    const float* __restrict__ Uh, float* __restrict__ out)
{
    const int tid = threadIdx.x;
    const int bb  = tid >> 6;         // 0..3  batch within CTA
    const int c4  = tid & 63;         // 0..63 column group
    const int c0  = c4 * 4;
    const int b   = blockIdx.x * 4 + bb;

    __shared__ float h_s[4][Hh];
    __shared__ float rh_s[4][Hh];

    float hreg[4] = {0.f, 0.f, 0.f, 0.f};
    *reinterpret_cast<float4*>(&h_s[bb][c0]) = make_float4(0.f, 0.f, 0.f, 0.f);
    __syncthreads();

    const size_t xbase = (size_t)b * Tt * Hh;

    for (int t = 0; t < Tt; t++) {
        const size_t xoff = xbase + (size_t)t * Hh + c0;
        const float4 vz = *reinterpret_cast<const float4*>(&g_xz[xoff]);
        const float4 vr = *reinterpret_cast<const float4*>(&g_xr[xoff]);
        const float4 vh = *reinterpret_cast<const float4*>(&g_xh[xoff]);

        float2 az0 = make_float2(vz.x, vz.y), az1 = make_float2(vz.z, vz.w);
        float2 ar0 = make_float2(vr.x, vr.y), ar1 = make_float2(vr.z, vr.w);

        // phase 1: z and r gate matvecs over h
#pragma unroll 8
        for (int k = 0; k < Hh; k++) {
            float4 uz = *reinterpret_cast<const float4*>(&Uz[(size_t)k * Hh + c0]);
            float4 ur = *reinterpret_cast<const float4*>(&Ur[(size_t)k * Hh + c0]);
            float hk = h_s[bb][k];
            float2 hh2 = make_float2(hk, hk);
            az0 = ffma2(make_float2(uz.x, uz.y), hh2, az0);
            az1 = ffma2(make_float2(uz.z, uz.w), hh2, az1);
            ar0 = ffma2(make_float2(ur.x, ur.y), hh2, ar0);
            ar1 = ffma2(make_float2(ur.z, ur.w), hh2, ar1);
        }

        float z0 = hsig(az0.x), z1 = hsig(az0.y), z2 = hsig(az1.x), z3 = hsig(az1.y);
        float r0 = hsig(ar0.x), r1 = hsig(ar0.y), r2 = hsig(ar1.x), r3 = hsig(ar1.y);

        *reinterpret_cast<float4*>(&rh_s[bb][c0]) =
            make_float4(r0 * hreg[0], r1 * hreg[1], r2 * hreg[2], r3 * hreg[3]);
        __syncthreads();

        // phase 2: candidate matvec over (r*h)
        float2 ah0 = make_float2(vh.x, vh.y), ah1 = make_float2(vh.z, vh.w);
#pragma unroll 8
        for (int k = 0; k < Hh; k++) {
            float4 uh = *reinterpret_cast<const float4*>(&Uh[(size_t)k * Hh + c0]);
            float rk = rh_s[bb][k];
            float2 rr2 = make_float2(rk, rk);
            ah0 = ffma2(make_float2(uh.x, uh.y), rr2, ah0);
            ah1 = ffma2(make_float2(uh.z, uh.w), rr2, ah1);
        }

        float cd0 = tanhf(ah0.x), cd1 = tanhf(ah0.y);
        float cd2 = tanhf(ah1.x), cd3 = tanhf(ah1.y);

        hreg[0] = z0 * hreg[0] + (1.f - z0) * cd0;
        hreg[1] = z1 * hreg[1] + (1.f - z1) * cd1;
        hreg[2] = z2 * hreg[2] + (1.f - z2) * cd2;
        hreg[3] = z3 * hreg[3] + (1.f - z3) * cd3;

        // all rh_s reads of this step are done in program order before here for
        // this thread; sync then publish new h for next step's phase 1.
        *reinterpret_cast<float4*>(&h_s[bb][c0]) =
            make_float4(hreg[0], hreg[1], hreg[2], hreg[3]);
        __syncthreads();
    }

    *reinterpret_cast<float4*>(&out[(size_t)b * Hh + c0]) =
        make_float4(hreg[0], hreg[1], hreg[2], hreg[3]);
}

extern "C" void kernel_launch(void* const* d_in, const int* in_sizes, int n_in,
                              void* d_out, int out_size) {
    (void)in_sizes; (void)n_in; (void)out_size;
    const float* x  = (const float*)d_in[0];
    const float* Wz = (const float*)d_in[1];
    const float* Wr = (const float*)d_in[2];
    const float* Wh = (const float*)d_in[3];
    const float* Uz = (const float*)d_in[4];
    const float* Ur = (const float*)d_in[5];
    const float* Uh = (const float*)d_in[6];
    const float* bz = (const float*)d_in[7];
    const float* br = (const float*)d_in[8];
    const float* bh = (const float*)d_in[9];
    float* out = (float*)d_out;

    dim3 pg(BT / 64, Hh / 128, 3);
    proj_kernel<<<pg, 256>>>(x, Wz, Wr, Wh, bz, br, bh);
    scan_kernel<<<Bb / 4, 256>>>(Uz, Ur, Uh, out);
}

// round 3
// speedup vs baseline: 4.1860x; 4.1860x over previous
#include <cuda_runtime.h>
#include <cuda_bf16.h>
#include <cstdint>

// Problem dims (fixed by the dataset)
#define Bb   128
#define Tt   1024
#define Dd   256
#define Hh   256
#define BT   (Bb * Tt)   // 131072

// Scratch for precomputed input projections (x@W + b), ~134MB each.
__device__ float g_xz[(size_t)BT * Hh];
__device__ float g_xr[(size_t)BT * Hh];
__device__ float g_xh[(size_t)BT * Hh];

// Packed dual-FP32 FMA (Blackwell FFMA2): d = a*b + c on both lanes.
__device__ __forceinline__ float2 ffma2(float2 a, float2 b, float2 c) {
    float2 d;
    asm("fma.rn.f32x2 %0, %1, %2, %3;"
        : "=l"(*reinterpret_cast<unsigned long long*>(&d))
        : "l"(*reinterpret_cast<const unsigned long long*>(&a)),
          "l"(*reinterpret_cast<const unsigned long long*>(&b)),
          "l"(*reinterpret_cast<const unsigned long long*>(&c)));
    return d;
}

__device__ __forceinline__ float hsig(float x) {
    return fminf(fmaxf(fmaf(x, 0.2f, 0.5f), 0.0f), 1.0f);
}

__device__ __forceinline__ uint32_t smem_u32(const void* p) {
    uint32_t a;
    asm("{ .reg .u64 t; cvta.to.shared.u64 t, %1; cvt.u32.u64 %0, t; }"
        : "=r"(a) : "l"(p));
    return a;
}

// Store a float2 into peer CTA 'rank' of the cluster at the same smem offset.
__device__ __forceinline__ void st_remote_f2(uint32_t laddr, int rank, float2 v) {
    uint32_t raddr;
    asm volatile("mapa.shared::cluster.u32 %0, %1, %2;"
                 : "=r"(raddr) : "r"(laddr), "r"(rank));
    asm volatile("st.shared::cluster.v2.f32 [%0], {%1, %2};"
                 :: "r"(raddr), "f"(v.x), "f"(v.y) : "memory");
}

__device__ __forceinline__ void cluster_sync_() {
    asm volatile("barrier.cluster.arrive.aligned;" ::: "memory");
    asm volatile("barrier.cluster.wait.aligned;" ::: "memory");
}

__device__ __forceinline__ uint32_t ctarank_() {
    uint32_t r;
    asm("mov.u32 %0, %%cluster_ctarank;" : "=r"(r));
    return r;
}

// ---------------------------------------------------------------------------
// Projection GEMM: out[r, c] = sum_k x[r,k] * W[k,c] + bias[c]
// (unchanged from R2 — correct, ~1ms; scan dominates)
// ---------------------------------------------------------------------------
__global__ __launch_bounds__(256) void proj_kernel(
    const float* __restrict__ x,
    const float* __restrict__ Wz, const float* __restrict__ Wr, const float* __restrict__ Wh,
    const float* __restrict__ bz, const float* __restrict__ br, const float* __restrict__ bh)
{
    const float* W; const float* bias; float* out;
    if (blockIdx.z == 0)      { W = Wz; bias = bz; out = g_xz; }
    else if (blockIdx.z == 1) { W = Wr; bias = br; out = g_xr; }
    else                      { W = Wh; bias = bh; out = g_xh; }

    const int row0 = blockIdx.x * 64;
    const int col0 = blockIdx.y * 128;
    const int tid  = threadIdx.x;

    __shared__ float As[16][65];
    __shared__ float Bs[16][128];

    const int trow = tid >> 4;
    const int tcol = tid & 15;
    const int r0   = trow * 4;
    const int c0   = tcol * 8;

    float2 bv[4];
#pragma unroll
    for (int j = 0; j < 4; j++)
        bv[j] = *reinterpret_cast<const float2*>(&bias[col0 + c0 + 2 * j]);

    float2 acc[4][4];
#pragma unroll
    for (int i = 0; i < 4; i++)
#pragma unroll
        for (int j = 0; j < 4; j++) acc[i][j] = bv[j];

    const int ar = tid >> 2;
    const int ak = (tid & 3) * 4;
    const int bk = tid >> 4;
    const int bc = (tid & 15) * 8;

    for (int kc = 0; kc < Dd; kc += 16) {
        float4 av = *reinterpret_cast<const float4*>(
            &x[(size_t)(row0 + ar) * Dd + kc + ak]);
        As[ak + 0][ar] = av.x;
        As[ak + 1][ar] = av.y;
        As[ak + 2][ar] = av.z;
        As[ak + 3][ar] = av.w;

        const float4* src = reinterpret_cast<const float4*>(
            &W[(size_t)(kc + bk) * Hh + col0 + bc]);
        *reinterpret_cast<float4*>(&Bs[bk][bc])     = src[0];
        *reinterpret_cast<float4*>(&Bs[bk][bc + 4]) = src[1];

        __syncthreads();

#pragma unroll
        for (int kk = 0; kk < 16; kk++) {
            float2 b0 = *reinterpret_cast<const float2*>(&Bs[kk][c0 + 0]);
            float2 b1 = *reinterpret_cast<const float2*>(&Bs[kk][c0 + 2]);
            float2 b2 = *reinterpret_cast<const float2*>(&Bs[kk][c0 + 4]);
            float2 b3 = *reinterpret_cast<const float2*>(&Bs[kk][c0 + 6]);
#pragma unroll
            for (int i = 0; i < 4; i++) {
                float a = As[kk][r0 + i];
                float2 a2 = make_float2(a, a);
                acc[i][0] = ffma2(b0, a2, acc[i][0]);
                acc[i][1] = ffma2(b1, a2, acc[i][1]);
                acc[i][2] = ffma2(b2, a2, acc[i][2]);
                acc[i][3] = ffma2(b3, a2, acc[i][3]);
            }
        }
        __syncthreads();
    }

#pragma unroll
    for (int i = 0; i < 4; i++) {
        float4 v0 = make_float4(acc[i][0].x, acc[i][0].y, acc[i][1].x, acc[i][1].y);
        float4 v1 = make_float4(acc[i][2].x, acc[i][2].y, acc[i][3].x, acc[i][3].y);
        float* dst = &out[(size_t)(row0 + r0 + i) * Hh + col0 + c0];
        *reinterpret_cast<float4*>(dst)     = v0;
        *reinterpret_cast<float4*>(dst + 4) = v1;
    }
}

// ---------------------------------------------------------------------------
// Cluster-cooperative scan.
// grid = 128 CTAs = 32 clusters x 4 CTAs, 256 threads/CTA.
// Cluster handles NB=4 batches. CTA rank r owns k-rows [64r, 64r+64) of all
// three U matrices, staged ONCE in SMEM. Reducer for output column c is rank
// c/64, so h and rh slices stay local — only partial sums cross CTAs.
// Thread layout (compute): cg = tid>>2 (64 col-groups x 4 cols), ksub = tid&3
//   (16 k each). Quad shfl-reduce over ksub; lane ksub==0 pushes partials to
//   the column-owner's inbox via st.shared::cluster.
// Thread layout (reduce):  b = tid>>6, cl = tid&63 (own 64-column slice).
// ---------------------------------------------------------------------------

// Shared layout (floats)
#define US_OFF   0                      // Us[3][64][256] = 49152 floats (192KB)
#define HT_OFF   49152                  // hT[64][4]   (k_local x batch)
#define RHT_OFF  (HT_OFF + 256)         // rhT[64][4]
#define INZR_OFF (RHT_OFF + 256)        // inbox_zr[src4][gate2][b4][cl64] = 2048
#define INH_OFF  (INZR_OFF + 2048)      // inbox_h[src4][b4][cl64] = 1024
#define SMEM_FLOATS (INH_OFF + 1024)    // 52736 floats = 210944 bytes

__global__ void __cluster_dims__(4, 1, 1) __launch_bounds__(256, 1)
scan_cluster_kernel(const float* __restrict__ Uz, const float* __restrict__ Ur,
                    const float* __restrict__ Uh, float* __restrict__ out)
{
    extern __shared__ float sm[];
    const int tid  = threadIdx.x;
    const int rank = (int)ctarank_();
    const int cluster_id = blockIdx.x >> 2;

    // ---- stage U k-slice: rows [64*rank, 64*rank+64) of Uz,Ur,Uh ----
    {
        const float* srcs[3] = {Uz, Ur, Uh};
#pragma unroll
        for (int m = 0; m < 3; m++) {
            const float* src = srcs[m] + (size_t)(64 * rank) * Hh;
            for (int i = tid; i < 64 * 64; i += 256) {   // float4 units
                int k = i >> 6, c4 = i & 63;
                *reinterpret_cast<float4*>(&sm[US_OFF + m * 16384 + k * 256 + c4 * 4]) =
                    *reinterpret_cast<const float4*>(&src[(size_t)k * Hh + c4 * 4]);
            }
        }
        if (tid < 256) sm[HT_OFF + tid] = 0.0f;   // hT init
    }
    __syncthreads();

    // compute-phase indices
    const int cg   = tid >> 2;         // 0..63 column group (4 cols)
    const int ksub = tid & 3;          // 0..3  k sub-slice (16 rows)
    const int c0   = cg * 4;
    const int dest = cg >> 4;          // rank owning these columns
    const int cl_w = (cg & 15) * 4;    // col_local at dest

    // reduce-phase indices
    const int rb  = tid >> 6;          // batch 0..3
    const int rcl = tid & 63;          // own column slice index
    const int cglob = rank * 64 + rcl;
    const int bglob = cluster_id * 4 + rb;
    const size_t xbase = ((size_t)bglob * Tt) * Hh + cglob;

    const uint32_t inzr_base = smem_u32(&sm[INZR_OFF]);
    const uint32_t inh_base  = smem_u32(&sm[INH_OFF]);

    float h_reg = 0.0f;                // h for (bglob, cglob), reduce-thread view

    const float* Uz_s = &sm[US_OFF + 0 * 16384];
    const float* Ur_s = &sm[US_OFF + 1 * 16384];
    const float* Uh_s = &sm[US_OFF + 2 * 16384];

    for (int t = 0; t < Tt; t++) {
        // prefetch this step's precomputed projections (DRAM, hidden under phase1)
        const size_t xoff = xbase + (size_t)t * Hh;
        const float xzv = g_xz[xoff];
        const float xrv = g_xr[xoff];
        const float xhv = g_xh[xoff];

        // ---------------- phase 1 partial: z and r over own k-slice ----------------
        float2 az[4][2], ar[4][2];
#pragma unroll
        for (int b = 0; b < 4; b++) {
            az[b][0] = az[b][1] = make_float2(0.f, 0.f);
            ar[b][0] = ar[b][1] = make_float2(0.f, 0.f);
        }
#pragma unroll 4
        for (int kk = 0; kk < 16; kk++) {
            const int k = ksub * 16 + kk;
            float4 uz = *reinterpret_cast<const float4*>(&Uz_s[k * 256 + c0]);
            float4 ur = *reinterpret_cast<const float4*>(&Ur_s[k * 256 + c0]);
            float4 h4 = *reinterpret_cast<const float4*>(&sm[HT_OFF + k * 4]);
            float2 uz01 = make_float2(uz.x, uz.y), uz23 = make_float2(uz.z, uz.w);
            float2 ur01 = make_float2(ur.x, ur.y), ur23 = make_float2(ur.z, ur.w);
            const float hb[4] = {h4.x, h4.y, h4.z, h4.w};
#pragma unroll
            for (int b = 0; b < 4; b++) {
                float2 h2 = make_float2(hb[b], hb[b]);
                az[b][0] = ffma2(uz01, h2, az[b][0]);
                az[b][1] = ffma2(uz23, h2, az[b][1]);
                ar[b][0] = ffma2(ur01, h2, ar[b][0]);
                ar[b][1] = ffma2(ur23, h2, ar[b][1]);
            }
        }
        // quad reduce over ksub (lanes t, t^1, t^2)
#pragma unroll
        for (int b = 0; b < 4; b++) {
#pragma unroll
            for (int j = 0; j < 2; j++) {
                az[b][j].x += __shfl_xor_sync(0xffffffffu, az[b][j].x, 1);
                az[b][j].y += __shfl_xor_sync(0xffffffffu, az[b][j].y, 1);
                az[b][j].x += __shfl_xor_sync(0xffffffffu, az[b][j].x, 2);
                az[b][j].y += __shfl_xor_sync(0xffffffffu, az[b][j].y, 2);
                ar[b][j].x += __shfl_xor_sync(0xffffffffu, ar[b][j].x, 1);
                ar[b][j].y += __shfl_xor_sync(0xffffffffu, ar[b][j].y, 1);
                ar[b][j].x += __shfl_xor_sync(0xffffffffu, ar[b][j].x, 2);
                ar[b][j].y += __shfl_xor_sync(0xffffffffu, ar[b][j].y, 2);
            }
        }
        if (ksub == 0) {
            // push CTA-partial to column owner's inbox: [src=rank][gate][b][cl]
#pragma unroll
            for (int b = 0; b < 4; b++) {
                uint32_t a_z = inzr_base + (((rank * 2 + 0) * 4 + b) * 64 + cl_w) * 4u;
                uint32_t a_r = inzr_base + (((rank * 2 + 1) * 4 + b) * 64 + cl_w) * 4u;
                st_remote_f2(a_z,     dest, az[b][0]);
                st_remote_f2(a_z + 8, dest, az[b][1]);
                st_remote_f2(a_r,     dest, ar[b][0]);
                st_remote_f2(a_r + 8, dest, ar[b][1]);
            }
        }
        cluster_sync_();   // all z/r partials delivered

        // ---------------- reduce z/r for own columns ----------------
        float sz = xzv, sr = xrv;
#pragma unroll
        for (int s = 0; s < 4; s++) {
            sz += sm[INZR_OFF + ((s * 2 + 0) * 4 + rb) * 64 + rcl];
            sr += sm[INZR_OFF + ((s * 2 + 1) * 4 + rb) * 64 + rcl];
        }
        const float z = hsig(sz);
        const float r = hsig(sr);
        sm[RHT_OFF + rcl * 4 + rb] = r * h_reg;
        __syncthreads();   // rhT ready for phase-2 readers

        // ---------------- phase 2 partial: candidate over own k-slice ----------------
        float2 ah[4][2];
#pragma unroll
        for (int b = 0; b < 4; b++) ah[b][0] = ah[b][1] = make_float2(0.f, 0.f);
#pragma unroll 4
        for (int kk = 0; kk < 16; kk++) {
            const int k = ksub * 16 + kk;
            float4 uh = *reinterpret_cast<const float4*>(&Uh_s[k * 256 + c0]);
            float4 r4 = *reinterpret_cast<const float4*>(&sm[RHT_OFF + k * 4]);
            float2 uh01 = make_float2(uh.x, uh.y), uh23 = make_float2(uh.z, uh.w);
            const float rbv[4] = {r4.x, r4.y, r4.z, r4.w};
#pragma unroll
            for (int b = 0; b < 4; b++) {
                float2 r2 = make_float2(rbv[b], rbv[b]);
                ah[b][0] = ffma2(uh01, r2, ah[b][0]);
                ah[b][1] = ffma2(uh23, r2, ah[b][1]);
            }
        }
#pragma unroll
        for (int b = 0; b < 4; b++) {
#pragma unroll
            for (int j = 0; j < 2; j++) {
                ah[b][j].x += __shfl_xor_sync(0xffffffffu, ah[b][j].x, 1);
                ah[b][j].y += __shfl_xor_sync(0xffffffffu, ah[b][j].y, 1);
                ah[b][j].x += __shfl_xor_sync(0xffffffffu, ah[b][j].x, 2);
                ah[b][j].y += __shfl_xor_sync(0xffffffffu, ah[b][j].y, 2);
            }
        }
        if (ksub == 0) {
#pragma unroll
            for (int b = 0; b < 4; b++) {
                uint32_t a_h = inh_base + ((rank * 4 + b) * 64 + cl_w) * 4u;
                st_remote_f2(a_h,     dest, ah[b][0]);
                st_remote_f2(a_h + 8, dest, ah[b][1]);
            }
        }
        cluster_sync_();   // all candidate partials delivered

        // ---------------- reduce candidate, update h ----------------
        float sh = xhv;
#pragma unroll
        for (int s = 0; s < 4; s++)
            sh += sm[INH_OFF + (s * 4 + rb) * 64 + rcl];
        const float hh = tanhf(sh);
        h_reg = z * h_reg + (1.0f - z) * hh;
        sm[HT_OFF + rcl * 4 + rb] = h_reg;
        __syncthreads();   // hT ready for next step's phase 1
    }

    out[(size_t)bglob * Hh + cglob] = h_reg;
}

extern "C" void kernel_launch(void* const* d_in, const int* in_sizes, int n_in,
                              void* d_out, int out_size) {
    (void)in_sizes; (void)n_in; (void)out_size;
    const float* x  = (const float*)d_in[0];
    const float* Wz = (const float*)d_in[1];
    const float* Wr = (const float*)d_in[2];
    const float* Wh = (const float*)d_in[3];
    const float* Uz = (const float*)d_in[4];
    const float* Ur = (const float*)d_in[5];
    const float* Uh = (const float*)d_in[6];
    const float* bz = (const float*)d_in[7];
    const float* br = (const float*)d_in[8];
    const float* bh = (const float*)d_in[9];
    float* out = (float*)d_out;

    static int smem_set = 0;
    if (!smem_set) {
        cudaFuncSetAttribute(scan_cluster_kernel,
                             cudaFuncAttributeMaxDynamicSharedMemorySize,
                             SMEM_FLOATS * sizeof(float));
        smem_set = 1;
    }

    dim3 pg(BT / 64, Hh / 128, 3);
    proj_kernel<<<pg, 256>>>(x, Wz, Wr, Wh, bz, br, bh);
    scan_cluster_kernel<<<Bb, 256, SMEM_FLOATS * sizeof(float)>>>(Uz, Ur, Uh, out);
}

// round 4
// speedup vs baseline: 7.0638x; 1.6875x over previous
#include <cuda_runtime.h>
#include <cuda_bf16.h>
#include <cstdint>

#define Bb   128
#define Tt   1024
#define Dd   256
#define Hh   256
#define BT   (Bb * Tt)

__device__ float g_xz[(size_t)BT * Hh];
__device__ float g_xr[(size_t)BT * Hh];
__device__ float g_xh[(size_t)BT * Hh];

__device__ __forceinline__ float2 ffma2(float2 a, float2 b, float2 c) {
    float2 d;
    asm("fma.rn.f32x2 %0, %1, %2, %3;"
        : "=l"(*reinterpret_cast<unsigned long long*>(&d))
        : "l"(*reinterpret_cast<const unsigned long long*>(&a)),
          "l"(*reinterpret_cast<const unsigned long long*>(&b)),
          "l"(*reinterpret_cast<const unsigned long long*>(&c)));
    return d;
}

__device__ __forceinline__ float hsig(float x) {
    return fminf(fmaxf(fmaf(x, 0.2f, 0.5f), 0.0f), 1.0f);
}

__device__ __forceinline__ uint32_t smem_u32(const void* p) {
    uint32_t a;
    asm("{ .reg .u64 t; cvta.to.shared.u64 t, %1; cvt.u32.u64 %0, t; }"
        : "=r"(a) : "l"(p));
    return a;
}

__device__ __forceinline__ void st_remote_f4(uint32_t laddr, int rank, float4 v) {
    uint32_t raddr;
    asm volatile("mapa.shared::cluster.u32 %0, %1, %2;"
                 : "=r"(raddr) : "r"(laddr), "r"(rank));
    asm volatile("st.shared::cluster.v4.f32 [%0], {%1, %2, %3, %4};"
                 :: "r"(raddr), "f"(v.x), "f"(v.y), "f"(v.z), "f"(v.w) : "memory");
}

__device__ __forceinline__ void cluster_sync_() {
    asm volatile("barrier.cluster.arrive.aligned;" ::: "memory");
    asm volatile("barrier.cluster.wait.aligned;" ::: "memory");
}

__device__ __forceinline__ uint32_t ctarank_() {
    uint32_t r;
    asm("mov.u32 %0, %%cluster_ctarank;" : "=r"(r));
    return r;
}

// 8-lane (ksub) butterfly reduce of a float2
__device__ __forceinline__ void red8(float2& v) {
    v.x += __shfl_xor_sync(0xffffffffu, v.x, 1);
    v.y += __shfl_xor_sync(0xffffffffu, v.y, 1);
    v.x += __shfl_xor_sync(0xffffffffu, v.x, 2);
    v.y += __shfl_xor_sync(0xffffffffu, v.y, 2);
    v.x += __shfl_xor_sync(0xffffffffu, v.x, 4);
    v.y += __shfl_xor_sync(0xffffffffu, v.y, 4);
}

// ---------------------------------------------------------------------------
// Projection GEMM: out[r,c] = sum_k x[r,k]*W[k,c] + bias[c]
// 64x128 tile, 256 threads; thread owns 4 rows x (cols {c0a..+3} U {c0b..+3}).
// ---------------------------------------------------------------------------
__global__ __launch_bounds__(256) void proj_kernel(
    const float* __restrict__ x,
    const float* __restrict__ Wz, const float* __restrict__ Wr, const float* __restrict__ Wh,
    const float* __restrict__ bz, const float* __restrict__ br, const float* __restrict__ bh)
{
    const float* W; const float* bias; float* out;
    if (blockIdx.z == 0)      { W = Wz; bias = bz; out = g_xz; }
    else if (blockIdx.z == 1) { W = Wr; bias = br; out = g_xr; }
    else                      { W = Wh; bias = bh; out = g_xh; }

    const int row0 = blockIdx.x * 64;
    const int col0 = blockIdx.y * 128;
    const int tid  = threadIdx.x;

    __shared__ float As[16][68];    // [k][row], padded stride for aligned float4
    __shared__ float Bs[16][128];   // [k][col]

    const int trow = tid >> 4;      // 0..15
    const int tcol = tid & 15;      // 0..15
    const int r0   = trow * 4;
    const int c0a  = tcol * 4;      // first col quad (0..60)
    const int c0b  = 64 + tcol * 4; // second col quad (64..124)

    float2 bv[4];
    bv[0] = *reinterpret_cast<const float2*>(&bias[col0 + c0a]);
    bv[1] = *reinterpret_cast<const float2*>(&bias[col0 + c0a + 2]);
    bv[2] = *reinterpret_cast<const float2*>(&bias[col0 + c0b]);
    bv[3] = *reinterpret_cast<const float2*>(&bias[col0 + c0b + 2]);

    float2 acc[4][4];
#pragma unroll
    for (int i = 0; i < 4; i++)
#pragma unroll
        for (int j = 0; j < 4; j++) acc[i][j] = bv[j];

    const int ar = tid >> 2;            // 0..63
    const int ak = (tid & 3) * 4;       // 0,4,8,12
    const int bk = tid >> 4;            // 0..15
    const int bc = (tid & 15) * 8;

    for (int kc = 0; kc < Dd; kc += 16) {
        float4 av = *reinterpret_cast<const float4*>(
            &x[(size_t)(row0 + ar) * Dd + kc + ak]);
        As[ak + 0][ar] = av.x;
        As[ak + 1][ar] = av.y;
        As[ak + 2][ar] = av.z;
        As[ak + 3][ar] = av.w;

        const float4* src = reinterpret_cast<const float4*>(
            &W[(size_t)(kc + bk) * Hh + col0 + bc]);
        *reinterpret_cast<float4*>(&Bs[bk][bc])     = src[0];
        *reinterpret_cast<float4*>(&Bs[bk][bc + 4]) = src[1];

        __syncthreads();

#pragma unroll
        for (int kk = 0; kk < 16; kk++) {
            float4 a4 = *reinterpret_cast<const float4*>(&As[kk][r0]);
            float4 ba = *reinterpret_cast<const float4*>(&Bs[kk][c0a]);
            float4 bb = *reinterpret_cast<const float4*>(&Bs[kk][c0b]);
            float2 b0 = make_float2(ba.x, ba.y), b1 = make_float2(ba.z, ba.w);
            float2 b2 = make_float2(bb.x, bb.y), b3 = make_float2(bb.z, bb.w);
            const float a[4] = {a4.x, a4.y, a4.z, a4.w};
#pragma unroll
            for (int i = 0; i < 4; i++) {
                float2 a2 = make_float2(a[i], a[i]);
                acc[i][0] = ffma2(b0, a2, acc[i][0]);
                acc[i][1] = ffma2(b1, a2, acc[i][1]);
                acc[i][2] = ffma2(b2, a2, acc[i][2]);
                acc[i][3] = ffma2(b3, a2, acc[i][3]);
            }
        }
        __syncthreads();
    }

#pragma unroll
    for (int i = 0; i < 4; i++) {
        float* dst = &out[(size_t)(row0 + r0 + i) * Hh + col0];
        *reinterpret_cast<float4*>(dst + c0a) =
            make_float4(acc[i][0].x, acc[i][0].y, acc[i][1].x, acc[i][1].y);
        *reinterpret_cast<float4*>(dst + c0b) =
            make_float4(acc[i][2].x, acc[i][2].y, acc[i][3].x, acc[i][3].y);
    }
}

// ---------------------------------------------------------------------------
// Cluster-cooperative scan, 512 threads/CTA, 32 clusters x 4 CTAs.
// CTA rank owns k-rows [64r,64r+64) of Uz/Ur/Uh in SMEM (swizzled), and the
// matching output columns — h and r*h stay CTA-local; only partial sums cross.
// Compute: cg=tid>>3 (4 cols), ksub=tid&7 (8 k each), 4 batches in registers.
// U row k stored rotated by 4*(k>>3) floats -> conflict-free across ksub.
// hT/rhT stored at k*4 + 4*(k>>3) -> 1-phase broadcast loads.
// ---------------------------------------------------------------------------
#define US_OFF   0                       // 3 * 64 * 256 = 49152 floats (192KB)
#define HT_OFF   49152                   // 288 floats (swizzled [k][b])
#define RHT_OFF  (HT_OFF + 288)
#define INZR_OFF (RHT_OFF + 288)         // [src4][gate2][b4][cl64] = 2048
#define INH_OFF  (INZR_OFF + 2048)       // [src4][b4][cl64] = 1024
#define SMEM_FLOATS (INH_OFF + 1024)     // 52800 floats = 211200 bytes

__global__ void __cluster_dims__(4, 1, 1) __launch_bounds__(512, 1)
scan_cluster_kernel(const float* __restrict__ Uz, const float* __restrict__ Ur,
                    const float* __restrict__ Uh, float* __restrict__ out)
{
    extern __shared__ float sm[];
    const int tid  = threadIdx.x;
    const int rank = (int)ctarank_();
    const int cluster_id = blockIdx.x >> 2;

    // ---- stage U k-slice with per-row column rotation ----
    {
        const float* srcs[3] = {Uz, Ur, Uh};
#pragma unroll
        for (int m = 0; m < 3; m++) {
            const float* src = srcs[m] + (size_t)(64 * rank) * Hh;
            for (int i = tid; i < 64 * 64; i += 512) {
                int k = i >> 6, c = (i & 63) * 4;
                int cs = (c + ((k >> 3) & 7) * 4) & 255;
                *reinterpret_cast<float4*>(&sm[US_OFF + m * 16384 + k * 256 + cs]) =
                    *reinterpret_cast<const float4*>(&src[(size_t)k * Hh + c]);
            }
        }
        if (tid < 256) {
            int k = tid >> 2, b = tid & 3;
            sm[HT_OFF + k * 4 + ((k >> 3) & 7) * 4 + b] = 0.0f;
        }
    }
    __syncthreads();

    // compute-phase indices
    const int cg   = tid >> 3;          // 0..63
    const int ksub = tid & 7;           // 0..7
    const int c0   = cg * 4;
    const int crot = (c0 + ksub * 4) & 255;   // rotation constant per thread
    const int dest = cg >> 4;
    const int cl_w = (cg & 15) * 4;
    const int hoff = ksub * 36;         // swizzled hT base for k=8*ksub+kk

    // reduce-phase indices (threads 0..255)
    const int rb    = (tid >> 6) & 3;
    const int rcl   = tid & 63;
    const int rrot  = ((rcl >> 3) & 7) * 4;
    const int cglob = rank * 64 + rcl;
    const int bglob = cluster_id * 4 + rb;
    const size_t xbase = ((size_t)bglob * Tt) * Hh + cglob;

    const uint32_t inzr_base = smem_u32(&sm[INZR_OFF]);
    const uint32_t inh_base  = smem_u32(&sm[INH_OFF]);

    const float* Uz_s = &sm[US_OFF + 0 * 16384];
    const float* Ur_s = &sm[US_OFF + 1 * 16384];
    const float* Uh_s = &sm[US_OFF + 2 * 16384];

    float h_reg = 0.0f, zkeep = 0.0f;

    for (int t = 0; t < Tt; t++) {
        float xzv = 0.f, xrv = 0.f, xhv = 0.f;
        if (tid < 256) {
            const size_t xoff = xbase + (size_t)t * Hh;
            xzv = g_xz[xoff];
            xrv = g_xr[xoff];
            xhv = g_xh[xoff];
        }

        // ---------------- phase 1: z,r partials over own 8 k ----------------
        float2 az[4][2], ar[4][2];
#pragma unroll
        for (int b = 0; b < 4; b++) {
            az[b][0] = az[b][1] = make_float2(0.f, 0.f);
            ar[b][0] = ar[b][1] = make_float2(0.f, 0.f);
        }
#pragma unroll
        for (int kk = 0; kk < 8; kk++) {
            const int krow = (ksub * 8 + kk) * 256 + crot;
            float4 uz = *reinterpret_cast<const float4*>(&Uz_s[krow]);
            float4 ur = *reinterpret_cast<const float4*>(&Ur_s[krow]);
            float4 h4 = *reinterpret_cast<const float4*>(&sm[HT_OFF + hoff + kk * 4]);
            float2 uz01 = make_float2(uz.x, uz.y), uz23 = make_float2(uz.z, uz.w);
            float2 ur01 = make_float2(ur.x, ur.y), ur23 = make_float2(ur.z, ur.w);
            const float hb[4] = {h4.x, h4.y, h4.z, h4.w};
#pragma unroll
            for (int b = 0; b < 4; b++) {
                float2 h2 = make_float2(hb[b], hb[b]);
                az[b][0] = ffma2(uz01, h2, az[b][0]);
                az[b][1] = ffma2(uz23, h2, az[b][1]);
                ar[b][0] = ffma2(ur01, h2, ar[b][0]);
                ar[b][1] = ffma2(ur23, h2, ar[b][1]);
            }
        }
#pragma unroll
        for (int b = 0; b < 4; b++) {
            red8(az[b][0]); red8(az[b][1]);
            red8(ar[b][0]); red8(ar[b][1]);
        }
        if (ksub == 0) {
#pragma unroll
            for (int b = 0; b < 4; b++) {
                uint32_t a_z = inzr_base + (((rank * 2 + 0) * 4 + b) * 64 + cl_w) * 4u;
                uint32_t a_r = inzr_base + (((rank * 2 + 1) * 4 + b) * 64 + cl_w) * 4u;
                st_remote_f4(a_z, dest, make_float4(az[b][0].x, az[b][0].y, az[b][1].x, az[b][1].y));
                st_remote_f4(a_r, dest, make_float4(ar[b][0].x, ar[b][0].y, ar[b][1].x, ar[b][1].y));
            }
        }
        cluster_sync_();

        // ---------------- reduce z,r; publish r*h ----------------
        if (tid < 256) {
            float sz = xzv, sr = xrv;
#pragma unroll
            for (int s = 0; s < 4; s++) {
                sz += sm[INZR_OFF + ((s * 2 + 0) * 4 + rb) * 64 + rcl];
                sr += sm[INZR_OFF + ((s * 2 + 1) * 4 + rb) * 64 + rcl];
            }
            zkeep = hsig(sz);
            const float r = hsig(sr);
            sm[RHT_OFF + rcl * 4 + rrot + rb] = r * h_reg;
        }
        __syncthreads();

        // ---------------- phase 2: candidate partials ----------------
        float2 ah[4][2];
#pragma unroll
        for (int b = 0; b < 4; b++) ah[b][0] = ah[b][1] = make_float2(0.f, 0.f);
#pragma unroll
        for (int kk = 0; kk < 8; kk++) {
            const int krow = (ksub * 8 + kk) * 256 + crot;
            float4 uh = *reinterpret_cast<const float4*>(&Uh_s[krow]);
            float4 r4 = *reinterpret_cast<const float4*>(&sm[RHT_OFF + hoff + kk * 4]);
            float2 uh01 = make_float2(uh.x, uh.y), uh23 = make_float2(uh.z, uh.w);
            const float rv[4] = {r4.x, r4.y, r4.z, r4.w};
#pragma unroll
            for (int b = 0; b < 4; b++) {
                float2 r2 = make_float2(rv[b], rv[b]);
                ah[b][0] = ffma2(uh01, r2, ah[b][0]);
                ah[b][1] = ffma2(uh23, r2, ah[b][1]);
            }
        }
#pragma unroll
        for (int b = 0; b < 4; b++) { red8(ah[b][0]); red8(ah[b][1]); }
        if (ksub == 0) {
#pragma unroll
            for (int b = 0; b < 4; b++) {
                uint32_t a_h = inh_base + ((rank * 4 + b) * 64 + cl_w) * 4u;
                st_remote_f4(a_h, dest, make_float4(ah[b][0].x, ah[b][0].y, ah[b][1].x, ah[b][1].y));
            }
        }
        cluster_sync_();

        // ---------------- reduce candidate, update h ----------------
        if (tid < 256) {
            float sh = xhv;
#pragma unroll
            for (int s = 0; s < 4; s++)
                sh += sm[INH_OFF + (s * 4 + rb) * 64 + rcl];
            const float hh = tanhf(sh);
            h_reg = zkeep * h_reg + (1.0f - zkeep) * hh;
            sm[HT_OFF + rcl * 4 + rrot + rb] = h_reg;
        }
        __syncthreads();
    }

    if (tid < 256)
        out[(size_t)bglob * Hh + cglob] = h_reg;
}

extern "C" void kernel_launch(void* const* d_in, const int* in_sizes, int n_in,
                              void* d_out, int out_size) {
    (void)in_sizes; (void)n_in; (void)out_size;
    const float* x  = (const float*)d_in[0];
    const float* Wz = (const float*)d_in[1];
    const float* Wr = (const float*)d_in[2];
    const float* Wh = (const float*)d_in[3];
    const float* Uz = (const float*)d_in[4];
    const float* Ur = (const float*)d_in[5];
    const float* Uh = (const float*)d_in[6];
    const float* bz = (const float*)d_in[7];
    const float* br = (const float*)d_in[8];
    const float* bh = (const float*)d_in[9];
    float* out = (float*)d_out;

    static int smem_set = 0;
    if (!smem_set) {
        cudaFuncSetAttribute(scan_cluster_kernel,
                             cudaFuncAttributeMaxDynamicSharedMemorySize,
                             SMEM_FLOATS * sizeof(float));
        smem_set = 1;
    }

    dim3 pg(BT / 64, Hh / 128, 3);
    proj_kernel<<<pg, 256>>>(x, Wz, Wr, Wh, bz, br, bh);
    scan_cluster_kernel<<<Bb, 512, SMEM_FLOATS * sizeof(float)>>>(Uz, Ur, Uh, out);
}

// round 5
// speedup vs baseline: 8.7938x; 1.2449x over previous
#include <cuda_runtime.h>
#include <cuda_bf16.h>
#include <cstdint>

#define Bb   128
#define Tt   1024
#define Dd   256
#define Hh   256
#define BT   (Bb * Tt)

__device__ float g_xz[(size_t)BT * Hh];
__device__ float g_xr[(size_t)BT * Hh];
__device__ float g_xh[(size_t)BT * Hh];

__device__ __forceinline__ float2 ffma2(float2 a, float2 b, float2 c) {
    float2 d;
    asm("fma.rn.f32x2 %0, %1, %2, %3;"
        : "=l"(*reinterpret_cast<unsigned long long*>(&d))
        : "l"(*reinterpret_cast<const unsigned long long*>(&a)),
          "l"(*reinterpret_cast<const unsigned long long*>(&b)),
          "l"(*reinterpret_cast<const unsigned long long*>(&c)));
    return d;
}

__device__ __forceinline__ float hsig(float x) {
    return fminf(fmaxf(fmaf(x, 0.2f, 0.5f), 0.0f), 1.0f);
}

__device__ __forceinline__ uint32_t smem_u32(const void* p) {
    uint32_t a;
    asm("{ .reg .u64 t; cvta.to.shared.u64 t, %1; cvt.u32.u64 %0, t; }"
        : "=r"(a) : "l"(p));
    return a;
}

__device__ __forceinline__ void st_remote_f4(uint32_t laddr, int rank, float4 v) {
    uint32_t raddr;
    asm volatile("mapa.shared::cluster.u32 %0, %1, %2;"
                 : "=r"(raddr) : "r"(laddr), "r"(rank));
    asm volatile("st.shared::cluster.v4.f32 [%0], {%1, %2, %3, %4};"
                 :: "r"(raddr), "f"(v.x), "f"(v.y), "f"(v.z), "f"(v.w) : "memory");
}

__device__ __forceinline__ void st_remote_f2(uint32_t laddr, int rank, float2 v) {
    uint32_t raddr;
    asm volatile("mapa.shared::cluster.u32 %0, %1, %2;"
                 : "=r"(raddr) : "r"(laddr), "r"(rank));
    asm volatile("st.shared::cluster.v2.f32 [%0], {%1, %2};"
                 :: "r"(raddr), "f"(v.x), "f"(v.y) : "memory");
}

__device__ __forceinline__ void cluster_sync_() {
    asm volatile("barrier.cluster.arrive.aligned;" ::: "memory");
    asm volatile("barrier.cluster.wait.aligned;" ::: "memory");
}

__device__ __forceinline__ uint32_t ctarank_() {
    uint32_t r;
    asm("mov.u32 %0, %%cluster_ctarank;" : "=r"(r));
    return r;
}

// ---------------------------------------------------------------------------
// Projection GEMM (unchanged from R4)
// ---------------------------------------------------------------------------
__global__ __launch_bounds__(256) void proj_kernel(
    const float* __restrict__ x,
    const float* __restrict__ Wz, const float* __restrict__ Wr, const float* __restrict__ Wh,
    const float* __restrict__ bz, const float* __restrict__ br, const float* __restrict__ bh)
{
    const float* W; const float* bias; float* out;
    if (blockIdx.z == 0)      { W = Wz; bias = bz; out = g_xz; }
    else if (blockIdx.z == 1) { W = Wr; bias = br; out = g_xr; }
    else                      { W = Wh; bias = bh; out = g_xh; }

    const int row0 = blockIdx.x * 64;
    const int col0 = blockIdx.y * 128;
    const int tid  = threadIdx.x;

    __shared__ float As[16][68];
    __shared__ float Bs[16][128];

    const int trow = tid >> 4;
    const int tcol = tid & 15;
    const int r0   = trow * 4;
    const int c0a  = tcol * 4;
    const int c0b  = 64 + tcol * 4;

    float2 bv[4];
    bv[0] = *reinterpret_cast<const float2*>(&bias[col0 + c0a]);
    bv[1] = *reinterpret_cast<const float2*>(&bias[col0 + c0a + 2]);
    bv[2] = *reinterpret_cast<const float2*>(&bias[col0 + c0b]);
    bv[3] = *reinterpret_cast<const float2*>(&bias[col0 + c0b + 2]);

    float2 acc[4][4];
#pragma unroll
    for (int i = 0; i < 4; i++)
#pragma unroll
        for (int j = 0; j < 4; j++) acc[i][j] = bv[j];

    const int ar = tid >> 2;
    const int ak = (tid & 3) * 4;
    const int bk = tid >> 4;
    const int bc = (tid & 15) * 8;

    for (int kc = 0; kc < Dd; kc += 16) {
        float4 av = *reinterpret_cast<const float4*>(
            &x[(size_t)(row0 + ar) * Dd + kc + ak]);
        As[ak + 0][ar] = av.x;
        As[ak + 1][ar] = av.y;
        As[ak + 2][ar] = av.z;
        As[ak + 3][ar] = av.w;

        const float4* src = reinterpret_cast<const float4*>(
            &W[(size_t)(kc + bk) * Hh + col0 + bc]);
        *reinterpret_cast<float4*>(&Bs[bk][bc])     = src[0];
        *reinterpret_cast<float4*>(&Bs[bk][bc + 4]) = src[1];

        __syncthreads();

#pragma unroll
        for (int kk = 0; kk < 16; kk++) {
            float4 a4 = *reinterpret_cast<const float4*>(&As[kk][r0]);
            float4 ba = *reinterpret_cast<const float4*>(&Bs[kk][c0a]);
            float4 bb = *reinterpret_cast<const float4*>(&Bs[kk][c0b]);
            float2 b0 = make_float2(ba.x, ba.y), b1 = make_float2(ba.z, ba.w);
            float2 b2 = make_float2(bb.x, bb.y), b3 = make_float2(bb.z, bb.w);
            const float a[4] = {a4.x, a4.y, a4.z, a4.w};
#pragma unroll
            for (int i = 0; i < 4; i++) {
                float2 a2 = make_float2(a[i], a[i]);
                acc[i][0] = ffma2(b0, a2, acc[i][0]);
                acc[i][1] = ffma2(b1, a2, acc[i][1]);
                acc[i][2] = ffma2(b2, a2, acc[i][2]);
                acc[i][3] = ffma2(b3, a2, acc[i][3]);
            }
        }
        __syncthreads();
    }

#pragma unroll
    for (int i = 0; i < 4; i++) {
        float* dst = &out[(size_t)(row0 + r0 + i) * Hh + col0];
        *reinterpret_cast<float4*>(dst + c0a) =
            make_float4(acc[i][0].x, acc[i][0].y, acc[i][1].x, acc[i][1].y);
        *reinterpret_cast<float4*>(dst + c0b) =
            make_float4(acc[i][2].x, acc[i][2].y, acc[i][3].x, acc[i][3].y);
    }
}

// ---------------------------------------------------------------------------
// Cluster scan R5: Uz/Ur register-resident (warp-split z|r), Uh in SMEM.
// 128 CTAs = 32 clusters x 4; 512 thr/CTA. CTA rank owns k-rows [64r,64r+64)
// and output cols [64r,64r+64). Phase1: warps 0-7 z-matvec, 8-15 r-matvec,
// each thread: 16 k x 4 cols from registers, 4 batches. Reduce-scatter shfl
// (12 per phase1 thread), every lane stores its own (b)-float4 partial to the
// column owner's inbox. Phase2: all 16 warps on Uh from SMEM (ksub=8),
// reduce-scatter (14), f2 stores. hT/rhT swizzle: swz(k)=4k+8*((k>>4)&3).
// ---------------------------------------------------------------------------
#define UH_OFF   0                       // 64*256 = 16384 floats (64KB)
#define HT_OFF   16384                   // 288 floats swizzled [k][b4]
#define RHT_OFF  (HT_OFF + 288)
#define INZR_OFF (RHT_OFF + 288)         // [src4][gate2][b4][cl64] = 2048
#define INH_OFF  (INZR_OFF + 2048)       // [src4][b4][cl64] = 1024
#define SMEM_FLOATS (INH_OFF + 1024)     // 20032 floats = 80128 bytes

__global__ void __cluster_dims__(4, 1, 1) __launch_bounds__(512, 1)
scan_cluster_kernel(const float* __restrict__ Uz, const float* __restrict__ Ur,
                    const float* __restrict__ Uh, float* __restrict__ out)
{
    extern __shared__ float sm[];
    const int tid  = threadIdx.x;
    const int rank = (int)ctarank_();
    const int cluster_id = blockIdx.x >> 2;

    // ---- stage Uh k-slice in SMEM with per-row rotation ----
    for (int i = tid; i < 64 * 64; i += 512) {
        int k = i >> 6, c = (i & 63) * 4;
        int cs = (c + ((k >> 3) & 7) * 4) & 255;
        *reinterpret_cast<float4*>(&sm[UH_OFF + k * 256 + cs]) =
            *reinterpret_cast<const float4*>(&Uh[(size_t)(64 * rank + k) * Hh + c]);
    }
    if (tid < 256) {
        int k = tid >> 2, b = tid & 3;
        sm[HT_OFF + k * 4 + ((k >> 4) & 3) * 8 + b] = 0.0f;
    }

    // ---- phase-1 indices & register-resident U slice ----
    const int gate = tid >> 8;              // 0 = z (warps 0-7), 1 = r
    const int p1cg = (tid & 255) >> 2;      // 0..63 column quad
    const int p1k  = tid & 3;               // ksub (16 k each)
    const int p1c0 = p1cg * 4;
    const int p1dst = p1cg >> 4;
    const int p1cl  = (p1cg & 15) * 4;
    const int p1hb  = HT_OFF + p1k * 72;    // swz base: k=p1k*16+kk -> 72*p1k+4kk

    float4 Ug[16];
    {
        const float* Usrc = gate ? Ur : Uz;
#pragma unroll
        for (int kk = 0; kk < 16; kk++)
            Ug[kk] = *reinterpret_cast<const float4*>(
                &Usrc[(size_t)(64 * rank + p1k * 16 + kk) * Hh + p1c0]);
    }

    // ---- phase-2 indices ----
    const int p2cg = tid >> 3;              // 0..63
    const int p2k  = tid & 7;               // ksub (8 k each)
    const int p2crot = (p2cg * 4 + p2k * 4) & 255;
    const int p2dst  = p2cg >> 4;
    const int p2cl   = (p2cg & 15) * 4;
    const int p2hb   = RHT_OFF + 32 * p2k + 8 * (p2k >> 1);  // swz base

    // ---- reduce-phase indices (tid < 256) ----
    const int rb    = (tid >> 6) & 3;
    const int rcl   = tid & 63;
    const int rswz  = rcl * 4 + ((rcl >> 4) & 3) * 8;
    const int cglob = rank * 64 + rcl;
    const int bglob = cluster_id * 4 + rb;
    const size_t xbase = ((size_t)bglob * Tt) * Hh + cglob;

    const uint32_t inzr_base = smem_u32(&sm[INZR_OFF]);
    const uint32_t inh_base  = smem_u32(&sm[INH_OFF]);

    float h_reg = 0.0f, zkeep = 0.0f;
    __syncthreads();

#pragma unroll 1
    for (int t = 0; t < Tt; t++) {
        float xzv = 0.f, xrv = 0.f, xhv = 0.f;
        if (tid < 256) {
            const size_t xoff = xbase + (size_t)t * Hh;
            xzv = g_xz[xoff];
            xrv = g_xr[xoff];
            xhv = g_xh[xoff];
        }

        // ============ phase 1: one gate matvec per warp-half ============
        float2 v[8];   // j = b*2 + cp
#pragma unroll
        for (int j = 0; j < 8; j++) v[j] = make_float2(0.f, 0.f);
#pragma unroll
        for (int kk = 0; kk < 16; kk++) {
            float4 h4 = *reinterpret_cast<const float4*>(&sm[p1hb + kk * 4]);
            float2 u01 = make_float2(Ug[kk].x, Ug[kk].y);
            float2 u23 = make_float2(Ug[kk].z, Ug[kk].w);
            const float hb[4] = {h4.x, h4.y, h4.z, h4.w};
#pragma unroll
            for (int b = 0; b < 4; b++) {
                float2 h2 = make_float2(hb[b], hb[b]);
                v[2 * b]     = ffma2(u01, h2, v[2 * b]);
                v[2 * b + 1] = ffma2(u23, h2, v[2 * b + 1]);
            }
        }
        // reduce-scatter over 4 ksub lanes (levels xor2, xor1)
        {
            const bool hi2 = (p1k >> 1) & 1;
#pragma unroll
            for (int j = 0; j < 4; j++) {
                float sx = hi2 ? v[j].x : v[j + 4].x;
                float sy = hi2 ? v[j].y : v[j + 4].y;
                float rx = __shfl_xor_sync(0xffffffffu, sx, 2);
                float ry = __shfl_xor_sync(0xffffffffu, sy, 2);
                if (hi2) { v[j + 4].x += rx; v[j + 4].y += ry; }
                else     { v[j].x     += rx; v[j].y     += ry; }
            }
            float2 w[4];
#pragma unroll
            for (int j = 0; j < 4; j++) {
                w[j].x = hi2 ? v[j + 4].x : v[j].x;
                w[j].y = hi2 ? v[j + 4].y : v[j].y;
            }
            const bool hi1 = p1k & 1;
#pragma unroll
            for (int j = 0; j < 2; j++) {
                float sx = hi1 ? w[j].x : w[j + 2].x;
                float sy = hi1 ? w[j].y : w[j + 2].y;
                float rx = __shfl_xor_sync(0xffffffffu, sx, 1);
                float ry = __shfl_xor_sync(0xffffffffu, sy, 1);
                if (hi1) { w[j + 2].x += rx; w[j + 2].y += ry; }
                else     { w[j].x     += rx; w[j].y     += ry; }
            }
            float2 f0, f1;
            f0.x = hi1 ? w[2].x : w[0].x;  f0.y = hi1 ? w[2].y : w[0].y;
            f1.x = hi1 ? w[3].x : w[1].x;  f1.y = hi1 ? w[3].y : w[1].y;
            // this lane owns batch = p1k, its gate, cols p1c0..+3
            uint32_t addr = inzr_base +
                (uint32_t)((((rank * 2 + gate) * 4 + p1k) * 64 + p1cl) * 4);
            st_remote_f4(addr, p1dst, make_float4(f0.x, f0.y, f1.x, f1.y));
        }
        cluster_sync_();

        // ============ reduce z,r; publish r*h ============
        if (tid < 256) {
            float sz = xzv, sr = xrv;
#pragma unroll
            for (int s = 0; s < 4; s++) {
                sz += sm[INZR_OFF + ((s * 2 + 0) * 4 + rb) * 64 + rcl];
                sr += sm[INZR_OFF + ((s * 2 + 1) * 4 + rb) * 64 + rcl];
            }
            zkeep = hsig(sz);
            const float r = hsig(sr);
            sm[RHT_OFF + rswz + rb] = r * h_reg;
        }
        __syncthreads();

        // ============ phase 2: candidate matvec (all warps, Uh SMEM) ============
#pragma unroll
        for (int j = 0; j < 8; j++) v[j] = make_float2(0.f, 0.f);
#pragma unroll
        for (int kk = 0; kk < 8; kk++) {
            const int krow = (p2k * 8 + kk) * 256 + p2crot;
            float4 uh = *reinterpret_cast<const float4*>(&sm[UH_OFF + krow]);
            float4 r4 = *reinterpret_cast<const float4*>(&sm[p2hb + kk * 4]);
            float2 u01 = make_float2(uh.x, uh.y);
            float2 u23 = make_float2(uh.z, uh.w);
            const float rv[4] = {r4.x, r4.y, r4.z, r4.w};
#pragma unroll
            for (int b = 0; b < 4; b++) {
                float2 r2 = make_float2(rv[b], rv[b]);
                v[2 * b]     = ffma2(u01, r2, v[2 * b]);
                v[2 * b + 1] = ffma2(u23, r2, v[2 * b + 1]);
            }
        }
        // reduce-scatter over 8 ksub lanes (levels xor4, xor2, xor1)
        {
            const bool h4b = (p2k >> 2) & 1;
#pragma unroll
            for (int j = 0; j < 4; j++) {
                float sx = h4b ? v[j].x : v[j + 4].x;
                float sy = h4b ? v[j].y : v[j + 4].y;
                float rx = __shfl_xor_sync(0xffffffffu, sx, 4);
                float ry = __shfl_xor_sync(0xffffffffu, sy, 4);
                if (h4b) { v[j + 4].x += rx; v[j + 4].y += ry; }
                else     { v[j].x     += rx; v[j].y     += ry; }
            }
            float2 w[4];
#pragma unroll
            for (int j = 0; j < 4; j++) {
                w[j].x = h4b ? v[j + 4].x : v[j].x;
                w[j].y = h4b ? v[j + 4].y : v[j].y;
            }
            const bool h2b = (p2k >> 1) & 1;
#pragma unroll
            for (int j = 0; j < 2; j++) {
                float sx = h2b ? w[j].x : w[j + 2].x;
                float sy = h2b ? w[j].y : w[j + 2].y;
                float rx = __shfl_xor_sync(0xffffffffu, sx, 2);
                float ry = __shfl_xor_sync(0xffffffffu, sy, 2);
                if (h2b) { w[j + 2].x += rx; w[j + 2].y += ry; }
                else     { w[j].x     += rx; w[j].y     += ry; }
            }
            float2 u0, u1;
            u0.x = h2b ? w[2].x : w[0].x;  u0.y = h2b ? w[2].y : w[0].y;
            u1.x = h2b ? w[3].x : w[1].x;  u1.y = h2b ? w[3].y : w[1].y;
            const bool h1b = p2k & 1;
            {
                float sx = h1b ? u0.x : u1.x;
                float sy = h1b ? u0.y : u1.y;
                float rx = __shfl_xor_sync(0xffffffffu, sx, 1);
                float ry = __shfl_xor_sync(0xffffffffu, sy, 1);
                if (h1b) { u1.x += rx; u1.y += ry; }
                else     { u0.x += rx; u0.y += ry; }
            }
            float2 fin;
            fin.x = h1b ? u1.x : u0.x;
            fin.y = h1b ? u1.y : u0.y;
            // lane owns batch = p2k>>1, col pair cp = p2k&1
            uint32_t addr = inh_base +
                (uint32_t)(((rank * 4 + (p2k >> 1)) * 64 + p2cl + (p2k & 1) * 2) * 4);
            st_remote_f2(addr, p2dst, fin);
        }
        cluster_sync_();

        // ============ reduce candidate, update h ============
        if (tid < 256) {
            float sh = xhv;
#pragma unroll
            for (int s = 0; s < 4; s++)
                sh += sm[INH_OFF + (s * 4 + rb) * 64 + rcl];
            const float hh = tanhf(sh);
            h_reg = zkeep * h_reg + (1.0f - zkeep) * hh;
            sm[HT_OFF + rswz + rb] = h_reg;
        }
        __syncthreads();
    }

    if (tid < 256)
        out[(size_t)bglob * Hh + cglob] = h_reg;
}

extern "C" void kernel_launch(void* const* d_in, const int* in_sizes, int n_in,
                              void* d_out, int out_size) {
    (void)in_sizes; (void)n_in; (void)out_size;
    const float* x  = (const float*)d_in[0];
    const float* Wz = (const float*)d_in[1];
    const float* Wr = (const float*)d_in[2];
    const float* Wh = (const float*)d_in[3];
    const float* Uz = (const float*)d_in[4];
    const float* Ur = (const float*)d_in[5];
    const float* Uh = (const float*)d_in[6];
    const float* bz = (const float*)d_in[7];
    const float* br = (const float*)d_in[8];
    const float* bh = (const float*)d_in[9];
    float* out = (float*)d_out;

    static int smem_set = 0;
    if (!smem_set) {
        cudaFuncSetAttribute(scan_cluster_kernel,
                             cudaFuncAttributeMaxDynamicSharedMemorySize,
                             SMEM_FLOATS * sizeof(float));
        smem_set = 1;
    }

    dim3 pg(BT / 64, Hh / 128, 3);
    proj_kernel<<<pg, 256>>>(x, Wz, Wr, Wh, bz, br, bh);
    scan_cluster_kernel<<<Bb, 512, SMEM_FLOATS * sizeof(float)>>>(Uz, Ur, Uh, out);
}

// round 6
// speedup vs baseline: 8.9587x; 1.0188x over previous
#include <cuda_runtime.h>
#include <cuda_bf16.h>
#include <cstdint>

#define Bb   128
#define Tt   1024
#define Dd   256
#define Hh   256
#define BT   (Bb * Tt)

__device__ float g_xz[(size_t)BT * Hh];
__device__ float g_xr[(size_t)BT * Hh];
__device__ float g_xh[(size_t)BT * Hh];

__device__ __forceinline__ float2 ffma2(float2 a, float2 b, float2 c) {
    float2 d;
    asm("fma.rn.f32x2 %0, %1, %2, %3;"
        : "=l"(*reinterpret_cast<unsigned long long*>(&d))
        : "l"(*reinterpret_cast<const unsigned long long*>(&a)),
          "l"(*reinterpret_cast<const unsigned long long*>(&b)),
          "l"(*reinterpret_cast<const unsigned long long*>(&c)));
    return d;
}

__device__ __forceinline__ float hsig(float x) {
    return fminf(fmaxf(fmaf(x, 0.2f, 0.5f), 0.0f), 1.0f);
}

__device__ __forceinline__ uint32_t smem_u32(const void* p) {
    uint32_t a;
    asm("{ .reg .u64 t; cvta.to.shared.u64 t, %1; cvt.u32.u64 %0, t; }"
        : "=r"(a) : "l"(p));
    return a;
}

__device__ __forceinline__ void st_remote_f4(uint32_t laddr, int rank, float4 v) {
    uint32_t raddr;
    asm volatile("mapa.shared::cluster.u32 %0, %1, %2;"
                 : "=r"(raddr) : "r"(laddr), "r"(rank));
    asm volatile("st.shared::cluster.v4.f32 [%0], {%1, %2, %3, %4};"
                 :: "r"(raddr), "f"(v.x), "f"(v.y), "f"(v.z), "f"(v.w) : "memory");
}

__device__ __forceinline__ void st_remote_f2(uint32_t laddr, int rank, float2 v) {
    uint32_t raddr;
    asm volatile("mapa.shared::cluster.u32 %0, %1, %2;"
                 : "=r"(raddr) : "r"(laddr), "r"(rank));
    asm volatile("st.shared::cluster.v2.f32 [%0], {%1, %2};"
                 :: "r"(raddr), "f"(v.x), "f"(v.y) : "memory");
}

__device__ __forceinline__ void cluster_sync_() {
    asm volatile("barrier.cluster.arrive.aligned;" ::: "memory");
    asm volatile("barrier.cluster.wait.aligned;" ::: "memory");
}

__device__ __forceinline__ uint32_t ctarank_() {
    uint32_t r;
    asm("mov.u32 %0, %%cluster_ctarank;" : "=r"(r));
    return r;
}

// Release-arrive on the mbarrier at local offset 'laddr' in peer CTA 'rank'.
__device__ __forceinline__ void mbar_arrive_remote(uint32_t laddr, int rank) {
    uint32_t raddr;
    asm volatile("mapa.shared::cluster.u32 %0, %1, %2;"
                 : "=r"(raddr) : "r"(laddr), "r"(rank));
    asm volatile("mbarrier.arrive.release.cluster.shared::cluster.b64 _, [%0];"
                 :: "r"(raddr) : "memory");
}

// Acquire-wait (cluster scope) on local mbarrier for given phase parity.
__device__ __forceinline__ void mbar_wait_parity(uint32_t addr, uint32_t parity) {
    asm volatile(
        "{\n\t"
        ".reg .pred P;\n\t"
        "WL_%=:\n\t"
        "mbarrier.try_wait.parity.acquire.cluster.shared::cta.b64 P, [%0], %1, 0x989680;\n\t"
        "@!P bra WL_%=;\n\t"
        "}"
        :: "r"(addr), "r"(parity) : "memory");
}

// ---------------------------------------------------------------------------
// Projection GEMM (unchanged)
// ---------------------------------------------------------------------------
__global__ __launch_bounds__(256) void proj_kernel(
    const float* __restrict__ x,
    const float* __restrict__ Wz, const float* __restrict__ Wr, const float* __restrict__ Wh,
    const float* __restrict__ bz, const float* __restrict__ br, const float* __restrict__ bh)
{
    const float* W; const float* bias; float* out;
    if (blockIdx.z == 0)      { W = Wz; bias = bz; out = g_xz; }
    else if (blockIdx.z == 1) { W = Wr; bias = br; out = g_xr; }
    else                      { W = Wh; bias = bh; out = g_xh; }

    const int row0 = blockIdx.x * 64;
    const int col0 = blockIdx.y * 128;
    const int tid  = threadIdx.x;

    __shared__ float As[16][68];
    __shared__ float Bs[16][128];

    const int trow = tid >> 4;
    const int tcol = tid & 15;
    const int r0   = trow * 4;
    const int c0a  = tcol * 4;
    const int c0b  = 64 + tcol * 4;

    float2 bv[4];
    bv[0] = *reinterpret_cast<const float2*>(&bias[col0 + c0a]);
    bv[1] = *reinterpret_cast<const float2*>(&bias[col0 + c0a + 2]);
    bv[2] = *reinterpret_cast<const float2*>(&bias[col0 + c0b]);
    bv[3] = *reinterpret_cast<const float2*>(&bias[col0 + c0b + 2]);

    float2 acc[4][4];
#pragma unroll
    for (int i = 0; i < 4; i++)
#pragma unroll
        for (int j = 0; j < 4; j++) acc[i][j] = bv[j];

    const int ar = tid >> 2;
    const int ak = (tid & 3) * 4;
    const int bk = tid >> 4;
    const int bc = (tid & 15) * 8;

    for (int kc = 0; kc < Dd; kc += 16) {
        float4 av = *reinterpret_cast<const float4*>(
            &x[(size_t)(row0 + ar) * Dd + kc + ak]);
        As[ak + 0][ar] = av.x;
        As[ak + 1][ar] = av.y;
        As[ak + 2][ar] = av.z;
        As[ak + 3][ar] = av.w;

        const float4* src = reinterpret_cast<const float4*>(
            &W[(size_t)(kc + bk) * Hh + col0 + bc]);
        *reinterpret_cast<float4*>(&Bs[bk][bc])     = src[0];
        *reinterpret_cast<float4*>(&Bs[bk][bc + 4]) = src[1];

        __syncthreads();

#pragma unroll
        for (int kk = 0; kk < 16; kk++) {
            float4 a4 = *reinterpret_cast<const float4*>(&As[kk][r0]);
            float4 ba = *reinterpret_cast<const float4*>(&Bs[kk][c0a]);
            float4 bb = *reinterpret_cast<const float4*>(&Bs[kk][c0b]);
            float2 b0 = make_float2(ba.x, ba.y), b1 = make_float2(ba.z, ba.w);
            float2 b2 = make_float2(bb.x, bb.y), b3 = make_float2(bb.z, bb.w);
            const float a[4] = {a4.x, a4.y, a4.z, a4.w};
#pragma unroll
            for (int i = 0; i < 4; i++) {
                float2 a2 = make_float2(a[i], a[i]);
                acc[i][0] = ffma2(b0, a2, acc[i][0]);
                acc[i][1] = ffma2(b1, a2, acc[i][1]);
                acc[i][2] = ffma2(b2, a2, acc[i][2]);
                acc[i][3] = ffma2(b3, a2, acc[i][3]);
            }
        }
        __syncthreads();
    }

#pragma unroll
    for (int i = 0; i < 4; i++) {
        float* dst = &out[(size_t)(row0 + r0 + i) * Hh + col0];
        *reinterpret_cast<float4*>(dst + c0a) =
            make_float4(acc[i][0].x, acc[i][0].y, acc[i][1].x, acc[i][1].y);
        *reinterpret_cast<float4*>(dst + c0b) =
            make_float4(acc[i][2].x, acc[i][2].y, acc[i][3].x, acc[i][3].y);
    }
}

// ---------------------------------------------------------------------------
// Cluster scan R6: R5 design + mbarrier inbox signaling (no cluster.sync in
// loop) + split zr-reduce across both thread halves.
// Each inbox mbar expects 16 producer-warp arrives (4 warps/CTA x 4 CTAs).
// ---------------------------------------------------------------------------
#define UH_OFF   0                       // 64*256 = 16384 floats (64KB)
#define HT_OFF   16384                   // 288 floats swizzled [k][b4]
#define RHT_OFF  (HT_OFF + 288)
#define INZR_OFF (RHT_OFF + 288)         // [src4][gate2][b4][cl64] = 2048
#define INH_OFF  (INZR_OFF + 2048)       // [src4][b4][cl64] = 1024
#define MBAR_OFF (INH_OFF + 1024)        // 2 mbarriers (16 bytes) = 4 floats
#define SMEM_FLOATS (MBAR_OFF + 4)

__global__ void __cluster_dims__(4, 1, 1) __launch_bounds__(512, 1)
scan_cluster_kernel(const float* __restrict__ Uz, const float* __restrict__ Ur,
                    const float* __restrict__ Uh, float* __restrict__ out)
{
    extern __shared__ float sm[];
    const int tid  = threadIdx.x;
    const int rank = (int)ctarank_();
    const int cluster_id = blockIdx.x >> 2;

    const uint32_t mbzr = smem_u32(&sm[MBAR_OFF]);
    const uint32_t mbh  = smem_u32(&sm[MBAR_OFF + 2]);

    // ---- stage Uh k-slice in SMEM with per-row rotation ----
    for (int i = tid; i < 64 * 64; i += 512) {
        int k = i >> 6, c = (i & 63) * 4;
        int cs = (c + ((k >> 3) & 7) * 4) & 255;
        *reinterpret_cast<float4*>(&sm[UH_OFF + k * 256 + cs]) =
            *reinterpret_cast<const float4*>(&Uh[(size_t)(64 * rank + k) * Hh + c]);
    }
    if (tid < 256) {
        int k = tid >> 2, b = tid & 3;
        sm[HT_OFF + k * 4 + ((k >> 4) & 3) * 8 + b] = 0.0f;
    }
    if (tid == 0) {
        asm volatile("mbarrier.init.shared.b64 [%0], %1;" :: "r"(mbzr), "r"(16) : "memory");
        asm volatile("mbarrier.init.shared.b64 [%0], %1;" :: "r"(mbh),  "r"(16) : "memory");
    }

    // ---- phase-1 indices & register-resident Uz/Ur slice ----
    const int gate = tid >> 8;              // 0 = z (warps 0-7), 1 = r
    const int p1cg = (tid & 255) >> 2;      // 0..63 column quad
    const int p1k  = tid & 3;               // ksub (16 k each)
    const int p1c0 = p1cg * 4;
    const int p1dst = p1cg >> 4;            // warp-uniform (8 cg per warp)
    const int p1cl  = (p1cg & 15) * 4;
    const int p1hb  = HT_OFF + p1k * 72;

    float4 Ug[16];
    {
        const float* Usrc = gate ? Ur : Uz;
#pragma unroll
        for (int kk = 0; kk < 16; kk++)
            Ug[kk] = *reinterpret_cast<const float4*>(
                &Usrc[(size_t)(64 * rank + p1k * 16 + kk) * Hh + p1c0]);
    }

    // ---- phase-2 indices ----
    const int p2cg = tid >> 3;              // 0..63
    const int p2k  = tid & 7;
    const int p2crot = (p2cg * 4 + p2k * 4) & 255;
    const int p2dst  = p2cg >> 4;           // warp-uniform (4 cg per warp)
    const int p2cl   = (p2cg & 15) * 4;
    const int p2hb   = RHT_OFF + 32 * p2k + 8 * (p2k >> 1);

    // ---- reduce-phase indices (both halves; rtid = tid mod 256) ----
    const int rtid  = tid & 255;
    const int rb    = rtid >> 6;
    const int rcl   = rtid & 63;
    const int rswz  = rcl * 4 + ((rcl >> 4) & 3) * 8;
    const int cglob = rank * 64 + rcl;
    const int bglob = cluster_id * 4 + rb;
    const size_t xbase = ((size_t)bglob * Tt) * Hh + cglob;

    const uint32_t inzr_base = smem_u32(&sm[INZR_OFF]);
    const uint32_t inh_base  = smem_u32(&sm[INH_OFF]);

    float h_reg = 0.0f, zkeep = 0.0f;
    __syncthreads();
    cluster_sync_();   // mbarrier init + Uh staging visible cluster-wide

#pragma unroll 1
    for (int t = 0; t < Tt; t++) {
        const uint32_t ph = (uint32_t)(t & 1);

        // step-local x values: lower half needs xz & xh, upper half needs xr
        float xzv = 0.f, xrv = 0.f, xhv = 0.f;
        {
            const size_t xoff = xbase + (size_t)t * Hh;
            if (tid < 256) { xzv = g_xz[xoff]; xhv = g_xh[xoff]; }
            else           { xrv = g_xr[xoff]; }
        }

        // ============ phase 1: one gate matvec per warp-half ============
        float2 v[8];   // j = b*2 + cp
#pragma unroll
        for (int j = 0; j < 8; j++) v[j] = make_float2(0.f, 0.f);
#pragma unroll
        for (int kk = 0; kk < 16; kk++) {
            float4 h4 = *reinterpret_cast<const float4*>(&sm[p1hb + kk * 4]);
            float2 u01 = make_float2(Ug[kk].x, Ug[kk].y);
            float2 u23 = make_float2(Ug[kk].z, Ug[kk].w);
            const float hb[4] = {h4.x, h4.y, h4.z, h4.w};
#pragma unroll
            for (int b = 0; b < 4; b++) {
                float2 h2 = make_float2(hb[b], hb[b]);
                v[2 * b]     = ffma2(u01, h2, v[2 * b]);
                v[2 * b + 1] = ffma2(u23, h2, v[2 * b + 1]);
            }
        }
        // reduce-scatter over 4 ksub lanes (xor2, xor1)
        {
            const bool hi2 = (p1k >> 1) & 1;
#pragma unroll
            for (int j = 0; j < 4; j++) {
                float sx = hi2 ? v[j].x : v[j + 4].x;
                float sy = hi2 ? v[j].y : v[j + 4].y;
                float rx = __shfl_xor_sync(0xffffffffu, sx, 2);
                float ry = __shfl_xor_sync(0xffffffffu, sy, 2);
                if (hi2) { v[j + 4].x += rx; v[j + 4].y += ry; }
                else     { v[j].x     += rx; v[j].y     += ry; }
            }
            float2 w[4];
#pragma unroll
            for (int j = 0; j < 4; j++) {
                w[j].x = hi2 ? v[j + 4].x : v[j].x;
                w[j].y = hi2 ? v[j + 4].y : v[j].y;
            }
            const bool hi1 = p1k & 1;
#pragma unroll
            for (int j = 0; j < 2; j++) {
                float sx = hi1 ? w[j].x : w[j + 2].x;
                float sy = hi1 ? w[j].y : w[j + 2].y;
                float rx = __shfl_xor_sync(0xffffffffu, sx, 1);
                float ry = __shfl_xor_sync(0xffffffffu, sy, 1);
                if (hi1) { w[j + 2].x += rx; w[j + 2].y += ry; }
                else     { w[j].x     += rx; w[j].y     += ry; }
            }
            float2 f0, f1;
            f0.x = hi1 ? w[2].x : w[0].x;  f0.y = hi1 ? w[2].y : w[0].y;
            f1.x = hi1 ? w[3].x : w[1].x;  f1.y = hi1 ? w[3].y : w[1].y;
            uint32_t addr = inzr_base +
                (uint32_t)((((rank * 2 + gate) * 4 + p1k) * 64 + p1cl) * 4);
            st_remote_f4(addr, p1dst, make_float4(f0.x, f0.y, f1.x, f1.y));
        }
        __syncwarp();
        if ((tid & 31) == 0) mbar_arrive_remote(mbzr, p1dst);

        // ============ reduce z,r; publish r*h ============
        mbar_wait_parity(mbzr, ph);
        if (tid < 256) {
            float sz = xzv;
#pragma unroll
            for (int s = 0; s < 4; s++)
                sz += sm[INZR_OFF + ((s * 2 + 0) * 4 + rb) * 64 + rcl];
            zkeep = hsig(sz);
        } else {
            float sr = xrv;
#pragma unroll
            for (int s = 0; s < 4; s++)
                sr += sm[INZR_OFF + ((s * 2 + 1) * 4 + rb) * 64 + rcl];
            const float r = hsig(sr);
            const float hprev = sm[HT_OFF + rswz + rb];
            sm[RHT_OFF + rswz + rb] = r * hprev;
        }
        __syncthreads();

        // ============ phase 2: candidate matvec (all warps, Uh SMEM) ============
#pragma unroll
        for (int j = 0; j < 8; j++) v[j] = make_float2(0.f, 0.f);
#pragma unroll
        for (int kk = 0; kk < 8; kk++) {
            const int krow = (p2k * 8 + kk) * 256 + p2crot;
            float4 uh = *reinterpret_cast<const float4*>(&sm[UH_OFF + krow]);
            float4 r4 = *reinterpret_cast<const float4*>(&sm[p2hb + kk * 4]);
            float2 u01 = make_float2(uh.x, uh.y);
            float2 u23 = make_float2(uh.z, uh.w);
            const float rv[4] = {r4.x, r4.y, r4.z, r4.w};
#pragma unroll
            for (int b = 0; b < 4; b++) {
                float2 r2 = make_float2(rv[b], rv[b]);
                v[2 * b]     = ffma2(u01, r2, v[2 * b]);
                v[2 * b + 1] = ffma2(u23, r2, v[2 * b + 1]);
            }
        }
        // reduce-scatter over 8 ksub lanes (xor4, xor2, xor1)
        {
            const bool h4b = (p2k >> 2) & 1;
#pragma unroll
            for (int j = 0; j < 4; j++) {
                float sx = h4b ? v[j].x : v[j + 4].x;
                float sy = h4b ? v[j].y : v[j + 4].y;
                float rx = __shfl_xor_sync(0xffffffffu, sx, 4);
                float ry = __shfl_xor_sync(0xffffffffu, sy, 4);
                if (h4b) { v[j + 4].x += rx; v[j + 4].y += ry; }
                else     { v[j].x     += rx; v[j].y     += ry; }
            }
            float2 w[4];
#pragma unroll
            for (int j = 0; j < 4; j++) {
                w[j].x = h4b ? v[j + 4].x : v[j].x;
                w[j].y = h4b ? v[j + 4].y : v[j].y;
            }
            const bool h2b = (p2k >> 1) & 1;
#pragma unroll
            for (int j = 0; j < 2; j++) {
                float sx = h2b ? w[j].x : w[j + 2].x;
                float sy = h2b ? w[j].y : w[j + 2].y;
                float rx = __shfl_xor_sync(0xffffffffu, sx, 2);
                float ry = __shfl_xor_sync(0xffffffffu, sy, 2);
                if (h2b) { w[j + 2].x += rx; w[j + 2].y += ry; }
                else     { w[j].x     += rx; w[j].y     += ry; }
            }
            float2 u0, u1;
            u0.x = h2b ? w[2].x : w[0].x;  u0.y = h2b ? w[2].y : w[0].y;
            u1.x = h2b ? w[3].x : w[1].x;  u1.y = h2b ? w[3].y : w[1].y;
            const bool h1b = p2k & 1;
            {
                float sx = h1b ? u0.x : u1.x;
                float sy = h1b ? u0.y : u1.y;
                float rx = __shfl_xor_sync(0xffffffffu, sx, 1);
                float ry = __shfl_xor_sync(0xffffffffu, sy, 1);
                if (h1b) { u1.x += rx; u1.y += ry; }
                else     { u0.x += rx; u0.y += ry; }
            }
            float2 fin;
            fin.x = h1b ? u1.x : u0.x;
            fin.y = h1b ? u1.y : u0.y;
            uint32_t addr = inh_base +
                (uint32_t)(((rank * 4 + (p2k >> 1)) * 64 + p2cl + (p2k & 1) * 2) * 4);
            st_remote_f2(addr, p2dst, fin);
        }
        __syncwarp();
        if ((tid & 31) == 0) mbar_arrive_remote(mbh, p2dst);

        // ============ reduce candidate, update h ============
        if (tid < 256) {
            mbar_wait_parity(mbh, ph);
            float sh = xhv;
#pragma unroll
            for (int s = 0; s < 4; s++)
                sh += sm[INH_OFF + (s * 4 + rb) * 64 + rcl];
            const float hh = tanhf(sh);
            h_reg = zkeep * h_reg + (1.0f - zkeep) * hh;
            sm[HT_OFF + rswz + rb] = h_reg;
        }
        __syncthreads();
    }

    if (tid < 256)
        out[(size_t)bglob * Hh + cglob] = h_reg;

    cluster_sync_();   // no CTA exits while peers may still store to its smem
}

extern "C" void kernel_launch(void* const* d_in, const int* in_sizes, int n_in,
                              void* d_out, int out_size) {
    (void)in_sizes; (void)n_in; (void)out_size;
    const float* x  = (const float*)d_in[0];
    const float* Wz = (const float*)d_in[1];
    const float* Wr = (const float*)d_in[2];
    const float* Wh = (const float*)d_in[3];
    const float* Uz = (const float*)d_in[4];
    const float* Ur = (const float*)d_in[5];
    const float* Uh = (const float*)d_in[6];
    const float* bz = (const float*)d_in[7];
    const float* br = (const float*)d_in[8];
    const float* bh = (const float*)d_in[9];
    float* out = (float*)d_out;

    static int smem_set = 0;
    if (!smem_set) {
        cudaFuncSetAttribute(scan_cluster_kernel,
                             cudaFuncAttributeMaxDynamicSharedMemorySize,
                             SMEM_FLOATS * sizeof(float));
        smem_set = 1;
    }

    dim3 pg(BT / 64, Hh / 128, 3);
    proj_kernel<<<pg, 256>>>(x, Wz, Wr, Wh, bz, br, bh);
    scan_cluster_kernel<<<Bb, 512, SMEM_FLOATS * sizeof(float)>>>(Uz, Ur, Uh, out);
}

// round 8
// speedup vs baseline: 10.1301x; 1.1308x over previous
#include <cuda_runtime.h>
#include <cuda_bf16.h>
#include <cstdint>

#define Bb   128
#define Tt   1024
#define Dd   256
#define Hh   256
#define BT   (Bb * Tt)

__device__ float g_xz[(size_t)BT * Hh];
__device__ float g_xr[(size_t)BT * Hh];
__device__ float g_xh[(size_t)BT * Hh];

__device__ __forceinline__ float2 ffma2(float2 a, float2 b, float2 c) {
    float2 d;
    asm("fma.rn.f32x2 %0, %1, %2, %3;"
        : "=l"(*reinterpret_cast<unsigned long long*>(&d))
        : "l"(*reinterpret_cast<const unsigned long long*>(&a)),
          "l"(*reinterpret_cast<const unsigned long long*>(&b)),
          "l"(*reinterpret_cast<const unsigned long long*>(&c)));
    return d;
}

__device__ __forceinline__ float hsig(float x) {
    return fminf(fmaxf(fmaf(x, 0.2f, 0.5f), 0.0f), 1.0f);
}

__device__ __forceinline__ uint32_t smem_u32(const void* p) {
    uint32_t a;
    asm("{ .reg .u64 t; cvta.to.shared.u64 t, %1; cvt.u32.u64 %0, t; }"
        : "=r"(a) : "l"(p));
    return a;
}

__device__ __forceinline__ void st_remote_f4(uint32_t laddr, int rank, float4 v) {
    uint32_t raddr;
    asm volatile("mapa.shared::cluster.u32 %0, %1, %2;"
                 : "=r"(raddr) : "r"(laddr), "r"(rank));
    asm volatile("st.shared::cluster.v4.f32 [%0], {%1, %2, %3, %4};"
                 :: "r"(raddr), "f"(v.x), "f"(v.y), "f"(v.z), "f"(v.w) : "memory");
}

__device__ __forceinline__ void st_remote_f2(uint32_t laddr, int rank, float2 v) {
    uint32_t raddr;
    asm volatile("mapa.shared::cluster.u32 %0, %1, %2;"
                 : "=r"(raddr) : "r"(laddr), "r"(rank));
    asm volatile("st.shared::cluster.v2.f32 [%0], {%1, %2};"
                 :: "r"(raddr), "f"(v.x), "f"(v.y) : "memory");
}

__device__ __forceinline__ void cluster_sync_() {
    asm volatile("barrier.cluster.arrive.aligned;" ::: "memory");
    asm volatile("barrier.cluster.wait.aligned;" ::: "memory");
}

__device__ __forceinline__ uint32_t ctarank_() {
    uint32_t r;
    asm("mov.u32 %0, %%cluster_ctarank;" : "=r"(r));
    return r;
}

__device__ __forceinline__ void mbar_arrive_remote(uint32_t laddr, int rank) {
    uint32_t raddr;
    asm volatile("mapa.shared::cluster.u32 %0, %1, %2;"
                 : "=r"(raddr) : "r"(laddr), "r"(rank));
    asm volatile("mbarrier.arrive.release.cluster.shared::cluster.b64 _, [%0];"
                 :: "r"(raddr) : "memory");
}

__device__ __forceinline__ void mbar_wait_parity(uint32_t addr, uint32_t parity) {
    asm volatile(
        "{\n\t"
        ".reg .pred P;\n\t"
        "WL_%=:\n\t"
        "mbarrier.try_wait.parity.acquire.cluster.shared::cta.b64 P, [%0], %1, 0x989680;\n\t"
        "@!P bra WL_%=;\n\t"
        "}"
        :: "r"(addr), "r"(parity) : "memory");
}

// ---------------------------------------------------------------------------
// HMMA projection (mma.sync bf16x3 split): g_x*[r,c] = x[r,:]@W*[:,c] + b*[c]
// Grid = BT/128, 256 threads (8 warps). Per CTA: 128-row x tile as bf16 hi/lo
// in smem (row stride 264 bf16 for conflict-free ldmatrix), loop 3 gates x 4
// n-chunks(64). Warp w owns rows [16w,16w+16); 8 n-tile accumulators (f32).
// D = Ahi*Bhi + Ahi*Blo + Alo*Bhi; accums store directly to gmem with bias.
// ---------------------------------------------------------------------------
#define RS     264                         // padded row stride in bf16
#define PA_HI  0                           // 128*264*2 = 67584 B
#define PA_LO  67584
#define PB_HI  135168                      // 64*264*2 = 33792 B
#define PB_LO  168960
#define PROJ_SMEM_BYTES 202752

__device__ __forceinline__ void ldsm_x4(uint32_t addr, uint32_t* r) {
    asm volatile("ldmatrix.sync.aligned.m8n8.x4.shared.b16 {%0,%1,%2,%3}, [%4];"
                 : "=r"(r[0]), "=r"(r[1]), "=r"(r[2]), "=r"(r[3]) : "r"(addr));
}
__device__ __forceinline__ void ldsm_x2(uint32_t addr, uint32_t* r) {
    asm volatile("ldmatrix.sync.aligned.m8n8.x2.shared.b16 {%0,%1}, [%2];"
                 : "=r"(r[0]), "=r"(r[1]) : "r"(addr));
}
__device__ __forceinline__ void mma_bf16(float* c, const uint32_t* a, const uint32_t* b) {
    asm volatile(
        "mma.sync.aligned.m16n8k16.row.col.f32.bf16.bf16.f32 "
        "{%0,%1,%2,%3}, {%4,%5,%6,%7}, {%8,%9}, {%0,%1,%2,%3};"
        : "+f"(c[0]), "+f"(c[1]), "+f"(c[2]), "+f"(c[3])
        : "r"(a[0]), "r"(a[1]), "r"(a[2]), "r"(a[3]), "r"(b[0]), "r"(b[1]));
}

__global__ __launch_bounds__(256, 1) void proj_mma_kernel(
    const float* __restrict__ x,
    const float* __restrict__ Wz, const float* __restrict__ Wr,
    const float* __restrict__ Wh,
    const float* __restrict__ bz, const float* __restrict__ br,
    const float* __restrict__ bh)
{
    extern __shared__ char dsm[];
    const uint32_t sbase = smem_u32(dsm);

    const int tid  = threadIdx.x;
    const int wid  = tid >> 5;
    const int lane = tid & 31;
    const int row0 = blockIdx.x * 128;

    // ---- convert x tile -> A_hi / A_lo ----
    for (int idx = tid; idx < 128 * 64; idx += 256) {
        int m = idx >> 6, kq = (idx & 63) << 2;
        float4 v = *reinterpret_cast<const float4*>(&x[(size_t)(row0 + m) * Dd + kq]);
        __nv_bfloat16 h0 = __float2bfloat16(v.x), h1 = __float2bfloat16(v.y);
        __nv_bfloat16 h2 = __float2bfloat16(v.z), h3 = __float2bfloat16(v.w);
        __nv_bfloat16 l0 = __float2bfloat16(v.x - __bfloat162float(h0));
        __nv_bfloat16 l1 = __float2bfloat16(v.y - __bfloat162float(h1));
        __nv_bfloat16 l2 = __float2bfloat16(v.z - __bfloat162float(h2));
        __nv_bfloat16 l3 = __float2bfloat16(v.w - __bfloat162float(h3));
        uint32_t off = (uint32_t)(m * RS + kq) * 2u;
        *reinterpret_cast<__nv_bfloat162*>(dsm + PA_HI + off)     = __halves2bfloat162(h0, h1);
        *reinterpret_cast<__nv_bfloat162*>(dsm + PA_HI + off + 4) = __halves2bfloat162(h2, h3);
        *reinterpret_cast<__nv_bfloat162*>(dsm + PA_LO + off)     = __halves2bfloat162(l0, l1);
        *reinterpret_cast<__nv_bfloat162*>(dsm + PA_LO + off + 4) = __halves2bfloat162(l2, l3);
    }

    // ---- ldmatrix lane pointers ----
    const int mloc = wid * 16 + (lane & 15);
    const int ako  = (lane >> 4) * 8;
    const uint32_t aptr_hi = sbase + PA_HI + (uint32_t)(mloc * RS + ako) * 2u;
    const uint32_t aptr_lo = sbase + PA_LO + (uint32_t)(mloc * RS + ako) * 2u;

    const int nrow = lane & 7;
    const int bko  = (lane & 8) ? 8 : 0;
    const uint32_t bptr_hi = sbase + PB_HI + (uint32_t)(nrow * RS + bko) * 2u;
    const uint32_t bptr_lo = sbase + PB_LO + (uint32_t)(nrow * RS + bko) * 2u;

    const int gid = lane >> 2;          // accum row within m-tile
    const int tig = lane & 3;           // accum col pair

    for (int g = 0; g < 3; g++) {
        const float* W  = (g == 0) ? Wz : (g == 1) ? Wr : Wh;
        const float* bs = (g == 0) ? bz : (g == 1) ? br : bh;
        float* outp     = (g == 0) ? g_xz : (g == 1) ? g_xr : g_xh;

        for (int nc = 0; nc < 4; nc++) {
            const int n0 = nc * 64;
            __syncthreads();   // prior chunk's ldmatrix reads complete

            // ---- load + convert B chunk: B[n][k] = W[k][n0+n], pack k-pairs ----
            for (int idx = tid; idx < 64 * 128; idx += 256) {
                int k2 = idx >> 6;       // k-pair 0..127
                int n  = idx & 63;
                float w0 = W[(size_t)(2 * k2) * Hh + n0 + n];
                float w1 = W[(size_t)(2 * k2 + 1) * Hh + n0 + n];
                __nv_bfloat16 h0 = __float2bfloat16(w0);
                __nv_bfloat16 h1 = __float2bfloat16(w1);
                __nv_bfloat16 l0 = __float2bfloat16(w0 - __bfloat162float(h0));
                __nv_bfloat16 l1 = __float2bfloat16(w1 - __bfloat162float(h1));
                uint32_t off = (uint32_t)(n * RS + 2 * k2) * 2u;
                *reinterpret_cast<__nv_bfloat162*>(dsm + PB_HI + off) = __halves2bfloat162(h0, h1);
                *reinterpret_cast<__nv_bfloat162*>(dsm + PB_LO + off) = __halves2bfloat162(l0, l1);
            }
            __syncthreads();

            // ---- MMA mainloop ----
            float acc[8][4];
#pragma unroll
            for (int nt = 0; nt < 8; nt++)
#pragma unroll
                for (int j = 0; j < 4; j++) acc[nt][j] = 0.0f;

#pragma unroll 4
            for (int ks = 0; ks < 16; ks++) {
                uint32_t ah[4], al[4];
                ldsm_x4(aptr_hi + ks * 32u, ah);
                ldsm_x4(aptr_lo + ks * 32u, al);
#pragma unroll
                for (int nt = 0; nt < 8; nt++) {
                    uint32_t bhf[2], blf[2];
                    const uint32_t boff = (uint32_t)(nt * 8 * RS) * 2u + ks * 32u;
                    ldsm_x2(bptr_hi + boff, bhf);
                    ldsm_x2(bptr_lo + boff, blf);
                    mma_bf16(acc[nt], ah, bhf);
                    mma_bf16(acc[nt], ah, blf);
                    mma_bf16(acc[nt], al, bhf);
                }
            }

            // ---- epilogue: bias + direct STG ----
            const int row = row0 + wid * 16 + gid;
#pragma unroll
            for (int nt = 0; nt < 8; nt++) {
                const int col = n0 + nt * 8 + tig * 2;
                float2 bv = *reinterpret_cast<const float2*>(&bs[col]);
                float2 v0 = make_float2(acc[nt][0] + bv.x, acc[nt][1] + bv.y);
                float2 v1 = make_float2(acc[nt][2] + bv.x, acc[nt][3] + bv.y);
                *reinterpret_cast<float2*>(&outp[(size_t)row * Hh + col])       = v0;
                *reinterpret_cast<float2*>(&outp[(size_t)(row + 8) * Hh + col]) = v1;
            }
        }
    }
}

// ---------------------------------------------------------------------------
// Cluster scan (identical to R6 — passed twice at 3.10ms)
// ---------------------------------------------------------------------------
#define UH_OFF   0
#define HT_OFF   16384
#define RHT_OFF  (HT_OFF + 288)
#define INZR_OFF (RHT_OFF + 288)
#define INH_OFF  (INZR_OFF + 2048)
#define MBAR_OFF (INH_OFF + 1024)
#define SMEM_FLOATS (MBAR_OFF + 4)

__global__ void __cluster_dims__(4, 1, 1) __launch_bounds__(512, 1)
scan_cluster_kernel(const float* __restrict__ Uz, const float* __restrict__ Ur,
                    const float* __restrict__ Uh, float* __restrict__ out)
{
    extern __shared__ float sm[];
    const int tid  = threadIdx.x;
    const int rank = (int)ctarank_();
    const int cluster_id = blockIdx.x >> 2;

    const uint32_t mbzr = smem_u32(&sm[MBAR_OFF]);
    const uint32_t mbh  = smem_u32(&sm[MBAR_OFF + 2]);

    for (int i = tid; i < 64 * 64; i += 512) {
        int k = i >> 6, c = (i & 63) * 4;
        int cs = (c + ((k >> 3) & 7) * 4) & 255;
        *reinterpret_cast<float4*>(&sm[UH_OFF + k * 256 + cs]) =
            *reinterpret_cast<const float4*>(&Uh[(size_t)(64 * rank + k) * Hh + c]);
    }
    if (tid < 256) {
        int k = tid >> 2, b = tid & 3;
        sm[HT_OFF + k * 4 + ((k >> 4) & 3) * 8 + b] = 0.0f;
    }
    if (tid == 0) {
        asm volatile("mbarrier.init.shared.b64 [%0], %1;" :: "r"(mbzr), "r"(16) : "memory");
        asm volatile("mbarrier.init.shared.b64 [%0], %1;" :: "r"(mbh),  "r"(16) : "memory");
    }

    const int gate = tid >> 8;
    const int p1cg = (tid & 255) >> 2;
    const int p1k  = tid & 3;
    const int p1c0 = p1cg * 4;
    const int p1dst = p1cg >> 4;
    const int p1cl  = (p1cg & 15) * 4;
    const int p1hb  = HT_OFF + p1k * 72;

    float4 Ug[16];
    {
        const float* Usrc = gate ? Ur : Uz;
#pragma unroll
        for (int kk = 0; kk < 16; kk++)
            Ug[kk] = *reinterpret_cast<const float4*>(
                &Usrc[(size_t)(64 * rank + p1k * 16 + kk) * Hh + p1c0]);
    }

    const int p2cg = tid >> 3;
    const int p2k  = tid & 7;
    const int p2crot = (p2cg * 4 + p2k * 4) & 255;
    const int p2dst  = p2cg >> 4;
    const int p2cl   = (p2cg & 15) * 4;
    const int p2hb   = RHT_OFF + 32 * p2k + 8 * (p2k >> 1);

    const int rtid  = tid & 255;
    const int rb    = rtid >> 6;
    const int rcl   = rtid & 63;
    const int rswz  = rcl * 4 + ((rcl >> 4) & 3) * 8;
    const int cglob = rank * 64 + rcl;
    const int bglob = cluster_id * 4 + rb;
    const size_t xbase = ((size_t)bglob * Tt) * Hh + cglob;

    const uint32_t inzr_base = smem_u32(&sm[INZR_OFF]);
    const uint32_t inh_base  = smem_u32(&sm[INH_OFF]);

    float h_reg = 0.0f, zkeep = 0.0f;
    __syncthreads();
    cluster_sync_();

#pragma unroll 1
    for (int t = 0; t < Tt; t++) {
        const uint32_t ph = (uint32_t)(t & 1);

        float xzv = 0.f, xrv = 0.f, xhv = 0.f;
        {
            const size_t xoff = xbase + (size_t)t * Hh;
            if (tid < 256) { xzv = g_xz[xoff]; xhv = g_xh[xoff]; }
            else           { xrv = g_xr[xoff]; }
        }

        float2 v[8];
#pragma unroll
        for (int j = 0; j < 8; j++) v[j] = make_float2(0.f, 0.f);
#pragma unroll
        for (int kk = 0; kk < 16; kk++) {
            float4 h4 = *reinterpret_cast<const float4*>(&sm[p1hb + kk * 4]);
            float2 u01 = make_float2(Ug[kk].x, Ug[kk].y);
            float2 u23 = make_float2(Ug[kk].z, Ug[kk].w);
            const float hb[4] = {h4.x, h4.y, h4.z, h4.w};
#pragma unroll
            for (int b = 0; b < 4; b++) {
                float2 h2 = make_float2(hb[b], hb[b]);
                v[2 * b]     = ffma2(u01, h2, v[2 * b]);
                v[2 * b + 1] = ffma2(u23, h2, v[2 * b + 1]);
            }
        }
        {
            const bool hi2 = (p1k >> 1) & 1;
#pragma unroll
            for (int j = 0; j < 4; j++) {
                float sx = hi2 ? v[j].x : v[j + 4].x;
                float sy = hi2 ? v[j].y : v[j + 4].y;
                float rx = __shfl_xor_sync(0xffffffffu, sx, 2);
                float ry = __shfl_xor_sync(0xffffffffu, sy, 2);
                if (hi2) { v[j + 4].x += rx; v[j + 4].y += ry; }
                else     { v[j].x     += rx; v[j].y     += ry; }
            }
            float2 w[4];
#pragma unroll
            for (int j = 0; j < 4; j++) {
                w[j].x = hi2 ? v[j + 4].x : v[j].x;
                w[j].y = hi2 ? v[j + 4].y : v[j].y;
            }
            const bool hi1 = p1k & 1;
#pragma unroll
            for (int j = 0; j < 2; j++) {
                float sx = hi1 ? w[j].x : w[j + 2].x;
                float sy = hi1 ? w[j].y : w[j + 2].y;
                float rx = __shfl_xor_sync(0xffffffffu, sx, 1);
                float ry = __shfl_xor_sync(0xffffffffu, sy, 1);
                if (hi1) { w[j + 2].x += rx; w[j + 2].y += ry; }
                else     { w[j].x     += rx; w[j].y     += ry; }
            }
            float2 f0, f1;
            f0.x = hi1 ? w[2].x : w[0].x;  f0.y = hi1 ? w[2].y : w[0].y;
            f1.x = hi1 ? w[3].x : w[1].x;  f1.y = hi1 ? w[3].y : w[1].y;
            uint32_t addr = inzr_base +
                (uint32_t)((((rank * 2 + gate) * 4 + p1k) * 64 + p1cl) * 4);
            st_remote_f4(addr, p1dst, make_float4(f0.x, f0.y, f1.x, f1.y));
        }
        __syncwarp();
        if ((tid & 31) == 0) mbar_arrive_remote(mbzr, p1dst);

        mbar_wait_parity(mbzr, ph);
        if (tid < 256) {
            float sz = xzv;
#pragma unroll
            for (int s = 0; s < 4; s++)
                sz += sm[INZR_OFF + ((s * 2 + 0) * 4 + rb) * 64 + rcl];
            zkeep = hsig(sz);
        } else {
            float sr = xrv;
#pragma unroll
            for (int s = 0; s < 4; s++)
                sr += sm[INZR_OFF + ((s * 2 + 1) * 4 + rb) * 64 + rcl];
            const float r = hsig(sr);
            const float hprev = sm[HT_OFF + rswz + rb];
            sm[RHT_OFF + rswz + rb] = r * hprev;
        }
        __syncthreads();

#pragma unroll
        for (int j = 0; j < 8; j++) v[j] = make_float2(0.f, 0.f);
#pragma unroll
        for (int kk = 0; kk < 8; kk++) {
            const int krow = (p2k * 8 + kk) * 256 + p2crot;
            float4 uh = *reinterpret_cast<const float4*>(&sm[UH_OFF + krow]);
            float4 r4 = *reinterpret_cast<const float4*>(&sm[p2hb + kk * 4]);
            float2 u01 = make_float2(uh.x, uh.y);
            float2 u23 = make_float2(uh.z, uh.w);
            const float rv[4] = {r4.x, r4.y, r4.z, r4.w};
#pragma unroll
            for (int b = 0; b < 4; b++) {
                float2 r2 = make_float2(rv[b], rv[b]);
                v[2 * b]     = ffma2(u01, r2, v[2 * b]);
                v[2 * b + 1] = ffma2(u23, r2, v[2 * b + 1]);
            }
        }
        {
            const bool h4b = (p2k >> 2) & 1;
#pragma unroll
            for (int j = 0; j < 4; j++) {
                float sx = h4b ? v[j].x : v[j + 4].x;
                float sy = h4b ? v[j].y : v[j + 4].y;
                float rx = __shfl_xor_sync(0xffffffffu, sx, 4);
                float ry = __shfl_xor_sync(0xffffffffu, sy, 4);
                if (h4b) { v[j + 4].x += rx; v[j + 4].y += ry; }
                else     { v[j].x     += rx; v[j].y     += ry; }
            }
            float2 w[4];
#pragma unroll
            for (int j = 0; j < 4; j++) {
                w[j].x = h4b ? v[j + 4].x : v[j].x;
                w[j].y = h4b ? v[j + 4].y : v[j].y;
            }
            const bool h2b = (p2k >> 1) & 1;
#pragma unroll
            for (int j = 0; j < 2; j++) {
                float sx = h2b ? w[j].x : w[j + 2].x;
                float sy = h2b ? w[j].y : w[j + 2].y;
                float rx = __shfl_xor_sync(0xffffffffu, sx, 2);
                float ry = __shfl_xor_sync(0xffffffffu, sy, 2);
                if (h2b) { w[j + 2].x += rx; w[j + 2].y += ry; }
                else     { w[j].x     += rx; w[j].y     += ry; }
            }
            float2 u0, u1;
            u0.x = h2b ? w[2].x : w[0].x;  u0.y = h2b ? w[2].y : w[0].y;
            u1.x = h2b ? w[3].x : w[1].x;  u1.y = h2b ? w[3].y : w[1].y;
            const bool h1b = p2k & 1;
            {
                float sx = h1b ? u0.x : u1.x;
                float sy = h1b ? u0.y : u1.y;
                float rx = __shfl_xor_sync(0xffffffffu, sx, 1);
                float ry = __shfl_xor_sync(0xffffffffu, sy, 1);
                if (h1b) { u1.x += rx; u1.y += ry; }
                else     { u0.x += rx; u0.y += ry; }
            }
            float2 fin;
            fin.x = h1b ? u1.x : u0.x;
            fin.y = h1b ? u1.y : u0.y;
            uint32_t addr = inh_base +
                (uint32_t)(((rank * 4 + (p2k >> 1)) * 64 + p2cl + (p2k & 1) * 2) * 4);
            st_remote_f2(addr, p2dst, fin);
        }
        __syncwarp();
        if ((tid & 31) == 0) mbar_arrive_remote(mbh, p2dst);

        if (tid < 256) {
            mbar_wait_parity(mbh, ph);
            float sh = xhv;
#pragma unroll
            for (int s = 0; s < 4; s++)
                sh += sm[INH_OFF + (s * 4 + rb) * 64 + rcl];
            const float hh = tanhf(sh);
            h_reg = zkeep * h_reg + (1.0f - zkeep) * hh;
            sm[HT_OFF + rswz + rb] = h_reg;
        }
        __syncthreads();
    }

    if (tid < 256)
        out[(size_t)bglob * Hh + cglob] = h_reg;

    cluster_sync_();
}

extern "C" void kernel_launch(void* const* d_in, const int* in_sizes, int n_in,
                              void* d_out, int out_size) {
    (void)in_sizes; (void)n_in; (void)out_size;
    const float* x  = (const float*)d_in[0];
    const float* Wz = (const float*)d_in[1];
    const float* Wr = (const float*)d_in[2];
    const float* Wh = (const float*)d_in[3];
    const float* Uz = (const float*)d_in[4];
    const float* Ur = (const float*)d_in[5];
    const float* Uh = (const float*)d_in[6];
    const float* bz = (const float*)d_in[7];
    const float* br = (const float*)d_in[8];
    const float* bh = (const float*)d_in[9];
    float* out = (float*)d_out;

    static int smem_set = 0;
    if (!smem_set) {
        cudaFuncSetAttribute(scan_cluster_kernel,
                             cudaFuncAttributeMaxDynamicSharedMemorySize,
                             SMEM_FLOATS * sizeof(float));
        cudaFuncSetAttribute(proj_mma_kernel,
                             cudaFuncAttributeMaxDynamicSharedMemorySize,
                             PROJ_SMEM_BYTES);
        smem_set = 1;
    }

    proj_mma_kernel<<<BT / 128, 256, PROJ_SMEM_BYTES>>>(x, Wz, Wr, Wh, bz, br, bh);
    scan_cluster_kernel<<<Bb, 512, SMEM_FLOATS * sizeof(float)>>>(Uz, Ur, Uh, out);
}

// round 9
// speedup vs baseline: 10.1607x; 1.0030x over previous
#include <cuda_runtime.h>
#include <cuda_bf16.h>
#include <cstdint>

#define Bb   128
#define Tt   1024
#define Dd   256
#define Hh   256
#define BT   (Bb * Tt)

__device__ float g_xz[(size_t)BT * Hh];
__device__ float g_xr[(size_t)BT * Hh];
__device__ float g_xh[(size_t)BT * Hh];

__device__ __forceinline__ float2 ffma2(float2 a, float2 b, float2 c) {
    float2 d;
    asm("fma.rn.f32x2 %0, %1, %2, %3;"
        : "=l"(*reinterpret_cast<unsigned long long*>(&d))
        : "l"(*reinterpret_cast<const unsigned long long*>(&a)),
          "l"(*reinterpret_cast<const unsigned long long*>(&b)),
          "l"(*reinterpret_cast<const unsigned long long*>(&c)));
    return d;
}

__device__ __forceinline__ float hsig(float x) {
    return fminf(fmaxf(fmaf(x, 0.2f, 0.5f), 0.0f), 1.0f);
}

__device__ __forceinline__ uint32_t smem_u32(const void* p) {
    uint32_t a;
    asm("{ .reg .u64 t; cvta.to.shared.u64 t, %1; cvt.u32.u64 %0, t; }"
        : "=r"(a) : "l"(p));
    return a;
}

__device__ __forceinline__ void st_remote_f4(uint32_t laddr, int rank, float4 v) {
    uint32_t raddr;
    asm volatile("mapa.shared::cluster.u32 %0, %1, %2;"
                 : "=r"(raddr) : "r"(laddr), "r"(rank));
    asm volatile("st.shared::cluster.v4.f32 [%0], {%1, %2, %3, %4};"
                 :: "r"(raddr), "f"(v.x), "f"(v.y), "f"(v.z), "f"(v.w) : "memory");
}

__device__ __forceinline__ void st_remote_f2(uint32_t laddr, int rank, float2 v) {
    uint32_t raddr;
    asm volatile("mapa.shared::cluster.u32 %0, %1, %2;"
                 : "=r"(raddr) : "r"(laddr), "r"(rank));
    asm volatile("st.shared::cluster.v2.f32 [%0], {%1, %2};"
                 :: "r"(raddr), "f"(v.x), "f"(v.y) : "memory");
}

__device__ __forceinline__ void cluster_sync_() {
    asm volatile("barrier.cluster.arrive.aligned;" ::: "memory");
    asm volatile("barrier.cluster.wait.aligned;" ::: "memory");
}

__device__ __forceinline__ uint32_t ctarank_() {
    uint32_t r;
    asm("mov.u32 %0, %%cluster_ctarank;" : "=r"(r));
    return r;
}

__device__ __forceinline__ void mbar_arrive_remote(uint32_t laddr, int rank) {
    uint32_t raddr;
    asm volatile("mapa.shared::cluster.u32 %0, %1, %2;"
                 : "=r"(raddr) : "r"(laddr), "r"(rank));
    asm volatile("mbarrier.arrive.release.cluster.shared::cluster.b64 _, [%0];"
                 :: "r"(raddr) : "memory");
}

__device__ __forceinline__ void mbar_wait_parity(uint32_t addr, uint32_t parity) {
    asm volatile(
        "{\n\t"
        ".reg .pred P;\n\t"
        "WL_%=:\n\t"
        "mbarrier.try_wait.parity.acquire.cluster.shared::cta.b64 P, [%0], %1, 0x989680;\n\t"
        "@!P bra WL_%=;\n\t"
        "}"
        :: "r"(addr), "r"(parity) : "memory");
}

// ---------------------------------------------------------------------------
// HMMA projection, m32n32 per warp (bf16x3 split).
// Grid = BT/128, 256 threads (8 warps = 4 m-groups x 2 n-groups).
// Per k-step per warp: 4 ldsm_x4 (A hi/lo x 2 m-tiles) + 8 ldsm_x2
// (B hi/lo x 4 n-tiles) + 24 mma — 32 smem wavefronts per 24 MMAs (was 40).
// ---------------------------------------------------------------------------
#define RS     264                         // padded row stride in bf16
#define PA_HI  0                           // 128*264*2 = 67584 B
#define PA_LO  67584
#define PB_HI  135168                      // 64*264*2 = 33792 B
#define PB_LO  168960
#define PROJ_SMEM_BYTES 202752

__device__ __forceinline__ void ldsm_x4(uint32_t addr, uint32_t* r) {
    asm volatile("ldmatrix.sync.aligned.m8n8.x4.shared.b16 {%0,%1,%2,%3}, [%4];"
                 : "=r"(r[0]), "=r"(r[1]), "=r"(r[2]), "=r"(r[3]) : "r"(addr));
}
__device__ __forceinline__ void ldsm_x2(uint32_t addr, uint32_t* r) {
    asm volatile("ldmatrix.sync.aligned.m8n8.x2.shared.b16 {%0,%1}, [%2];"
                 : "=r"(r[0]), "=r"(r[1]) : "r"(addr));
}
__device__ __forceinline__ void mma_bf16(float* c, const uint32_t* a, const uint32_t* b) {
    asm volatile(
        "mma.sync.aligned.m16n8k16.row.col.f32.bf16.bf16.f32 "
        "{%0,%1,%2,%3}, {%4,%5,%6,%7}, {%8,%9}, {%0,%1,%2,%3};"
        : "+f"(c[0]), "+f"(c[1]), "+f"(c[2]), "+f"(c[3])
        : "r"(a[0]), "r"(a[1]), "r"(a[2]), "r"(a[3]), "r"(b[0]), "r"(b[1]));
}

__global__ __launch_bounds__(256, 1) void proj_mma_kernel(
    const float* __restrict__ x,
    const float* __restrict__ Wz, const float* __restrict__ Wr,
    const float* __restrict__ Wh,
    const float* __restrict__ bz, const float* __restrict__ br,
    const float* __restrict__ bh)
{
    extern __shared__ char dsm[];
    const uint32_t sbase = smem_u32(dsm);

    const int tid  = threadIdx.x;
    const int wid  = tid >> 5;
    const int lane = tid & 31;
    const int row0 = blockIdx.x * 128;
    const int mg   = wid >> 1;          // 0..3 (m-group of 32 rows)
    const int ng   = wid & 1;           // 0..1 (n-group of 32 cols)

    // ---- convert x tile -> A_hi / A_lo ----
    for (int idx = tid; idx < 128 * 64; idx += 256) {
        int m = idx >> 6, kq = (idx & 63) << 2;
        float4 v = *reinterpret_cast<const float4*>(&x[(size_t)(row0 + m) * Dd + kq]);
        __nv_bfloat16 h0 = __float2bfloat16(v.x), h1 = __float2bfloat16(v.y);
        __nv_bfloat16 h2 = __float2bfloat16(v.z), h3 = __float2bfloat16(v.w);
        __nv_bfloat16 l0 = __float2bfloat16(v.x - __bfloat162float(h0));
        __nv_bfloat16 l1 = __float2bfloat16(v.y - __bfloat162float(h1));
        __nv_bfloat16 l2 = __float2bfloat16(v.z - __bfloat162float(h2));
        __nv_bfloat16 l3 = __float2bfloat16(v.w - __bfloat162float(h3));
        uint32_t off = (uint32_t)(m * RS + kq) * 2u;
        *reinterpret_cast<__nv_bfloat162*>(dsm + PA_HI + off)     = __halves2bfloat162(h0, h1);
        *reinterpret_cast<__nv_bfloat162*>(dsm + PA_HI + off + 4) = __halves2bfloat162(h2, h3);
        *reinterpret_cast<__nv_bfloat162*>(dsm + PA_LO + off)     = __halves2bfloat162(l0, l1);
        *reinterpret_cast<__nv_bfloat162*>(dsm + PA_LO + off + 4) = __halves2bfloat162(l2, l3);
    }

    // ---- ldmatrix lane pointers ----
    // A: m-tile mt rows = 32*mg + 16*mt + (lane&15), k-half = (lane>>4)*8
    const int arow = 32 * mg + (lane & 15);
    const int ako  = (lane >> 4) * 8;
    const uint32_t ah0 = sbase + PA_HI + (uint32_t)(arow * RS + ako) * 2u;
    const uint32_t ah1 = ah0 + (uint32_t)(16 * RS) * 2u;
    const uint32_t al0 = sbase + PA_LO + (uint32_t)(arow * RS + ako) * 2u;
    const uint32_t al1 = al0 + (uint32_t)(16 * RS) * 2u;

    // B: n-tile nt rows = 32*ng + 8*nt + (lane&7), k-half = (lane&8)?8:0
    const int nrow = 32 * ng + (lane & 7);
    const int bko  = (lane & 8) ? 8 : 0;
    const uint32_t bph = sbase + PB_HI + (uint32_t)(nrow * RS + bko) * 2u;
    const uint32_t bpl = sbase + PB_LO + (uint32_t)(nrow * RS + bko) * 2u;

    const int gid = lane >> 2;
    const int tig = lane & 3;

    for (int g = 0; g < 3; g++) {
        const float* W  = (g == 0) ? Wz : (g == 1) ? Wr : Wh;
        const float* bs = (g == 0) ? bz : (g == 1) ? br : bh;
        float* outp     = (g == 0) ? g_xz : (g == 1) ? g_xr : g_xh;

        for (int nc = 0; nc < 4; nc++) {
            const int n0 = nc * 64;
            __syncthreads();   // prior chunk's ldmatrix reads complete

            // ---- load + convert B chunk: B[n][k] = W[k][n0+n], pack k-pairs ----
            for (int idx = tid; idx < 64 * 128; idx += 256) {
                int k2 = idx >> 6;
                int n  = idx & 63;
                float w0 = W[(size_t)(2 * k2) * Hh + n0 + n];
                float w1 = W[(size_t)(2 * k2 + 1) * Hh + n0 + n];
                __nv_bfloat16 h0 = __float2bfloat16(w0);
                __nv_bfloat16 h1 = __float2bfloat16(w1);
                __nv_bfloat16 l0 = __float2bfloat16(w0 - __bfloat162float(h0));
                __nv_bfloat16 l1 = __float2bfloat16(w1 - __bfloat162float(h1));
                uint32_t off = (uint32_t)(n * RS + 2 * k2) * 2u;
                *reinterpret_cast<__nv_bfloat162*>(dsm + PB_HI + off) = __halves2bfloat162(h0, h1);
                *reinterpret_cast<__nv_bfloat162*>(dsm + PB_LO + off) = __halves2bfloat162(l0, l1);
            }
            __syncthreads();

            // ---- MMA mainloop (m32n32 per warp) ----
            float acc[2][4][4];
#pragma unroll
            for (int mt = 0; mt < 2; mt++)
#pragma unroll
                for (int nt = 0; nt < 4; nt++)
#pragma unroll
                    for (int j = 0; j < 4; j++) acc[mt][nt][j] = 0.0f;

#pragma unroll 4
            for (int ks = 0; ks < 16; ks++) {
                const uint32_t ko = (uint32_t)ks * 32u;
                uint32_t afh[2][4], afl[2][4];
                ldsm_x4(ah0 + ko, afh[0]);
                ldsm_x4(ah1 + ko, afh[1]);
                ldsm_x4(al0 + ko, afl[0]);
                ldsm_x4(al1 + ko, afl[1]);
#pragma unroll
                for (int nt = 0; nt < 4; nt++) {
                    const uint32_t boff = (uint32_t)(nt * 8 * RS) * 2u + ko;
                    uint32_t bfh[2], bfl[2];
                    ldsm_x2(bph + boff, bfh);
                    ldsm_x2(bpl + boff, bfl);
#pragma unroll
                    for (int mt = 0; mt < 2; mt++) {
                        mma_bf16(acc[mt][nt], afh[mt], bfh);
                        mma_bf16(acc[mt][nt], afh[mt], bfl);
                        mma_bf16(acc[mt][nt], afl[mt], bfh);
                    }
                }
            }

            // ---- epilogue: bias + direct STG ----
#pragma unroll
            for (int mt = 0; mt < 2; mt++) {
                const int row = row0 + 32 * mg + 16 * mt + gid;
#pragma unroll
                for (int nt = 0; nt < 4; nt++) {
                    const int col = n0 + 32 * ng + 8 * nt + tig * 2;
                    float2 bv = *reinterpret_cast<const float2*>(&bs[col]);
                    float2 v0 = make_float2(acc[mt][nt][0] + bv.x, acc[mt][nt][1] + bv.y);
                    float2 v1 = make_float2(acc[mt][nt][2] + bv.x, acc[mt][nt][3] + bv.y);
                    *reinterpret_cast<float2*>(&outp[(size_t)row * Hh + col])       = v0;
                    *reinterpret_cast<float2*>(&outp[(size_t)(row + 8) * Hh + col]) = v1;
                }
            }
        }
    }
}

// ---------------------------------------------------------------------------
// Cluster scan (identical to R6/R8 — passed three times at 3.10ms)
// ---------------------------------------------------------------------------
#define UH_OFF   0
#define HT_OFF   16384
#define RHT_OFF  (HT_OFF + 288)
#define INZR_OFF (RHT_OFF + 288)
#define INH_OFF  (INZR_OFF + 2048)
#define MBAR_OFF (INH_OFF + 1024)
#define SMEM_FLOATS (MBAR_OFF + 4)

__global__ void __cluster_dims__(4, 1, 1) __launch_bounds__(512, 1)
scan_cluster_kernel(const float* __restrict__ Uz, const float* __restrict__ Ur,
                    const float* __restrict__ Uh, float* __restrict__ out)
{
    extern __shared__ float sm[];
    const int tid  = threadIdx.x;
    const int rank = (int)ctarank_();
    const int cluster_id = blockIdx.x >> 2;

    const uint32_t mbzr = smem_u32(&sm[MBAR_OFF]);
    const uint32_t mbh  = smem_u32(&sm[MBAR_OFF + 2]);

    for (int i = tid; i < 64 * 64; i += 512) {
        int k = i >> 6, c = (i & 63) * 4;
        int cs = (c + ((k >> 3) & 7) * 4) & 255;
        *reinterpret_cast<float4*>(&sm[UH_OFF + k * 256 + cs]) =
            *reinterpret_cast<const float4*>(&Uh[(size_t)(64 * rank + k) * Hh + c]);
    }
    if (tid < 256) {
        int k = tid >> 2, b = tid & 3;
        sm[HT_OFF + k * 4 + ((k >> 4) & 3) * 8 + b] = 0.0f;
    }
    if (tid == 0) {
        asm volatile("mbarrier.init.shared.b64 [%0], %1;" :: "r"(mbzr), "r"(16) : "memory");
        asm volatile("mbarrier.init.shared.b64 [%0], %1;" :: "r"(mbh),  "r"(16) : "memory");
    }

    const int gate = tid >> 8;
    const int p1cg = (tid & 255) >> 2;
    const int p1k  = tid & 3;
    const int p1c0 = p1cg * 4;
    const int p1dst = p1cg >> 4;
    const int p1cl  = (p1cg & 15) * 4;
    const int p1hb  = HT_OFF + p1k * 72;

    float4 Ug[16];
    {
        const float* Usrc = gate ? Ur : Uz;
#pragma unroll
        for (int kk = 0; kk < 16; kk++)
            Ug[kk] = *reinterpret_cast<const float4*>(
                &Usrc[(size_t)(64 * rank + p1k * 16 + kk) * Hh + p1c0]);
    }

    const int p2cg = tid >> 3;
    const int p2k  = tid & 7;
    const int p2crot = (p2cg * 4 + p2k * 4) & 255;
    const int p2dst  = p2cg >> 4;
    const int p2cl   = (p2cg & 15) * 4;
    const int p2hb   = RHT_OFF + 32 * p2k + 8 * (p2k >> 1);

    const int rtid  = tid & 255;
    const int rb    = rtid >> 6;
    const int rcl   = rtid & 63;
    const int rswz  = rcl * 4 + ((rcl >> 4) & 3) * 8;
    const int cglob = rank * 64 + rcl;
    const int bglob = cluster_id * 4 + rb;
    const size_t xbase = ((size_t)bglob * Tt) * Hh + cglob;

    const uint32_t inzr_base = smem_u32(&sm[INZR_OFF]);
    const uint32_t inh_base  = smem_u32(&sm[INH_OFF]);

    float h_reg = 0.0f, zkeep = 0.0f;
    __syncthreads();
    cluster_sync_();

#pragma unroll 1
    for (int t = 0; t < Tt; t++) {
        const uint32_t ph = (uint32_t)(t & 1);

        float xzv = 0.f, xrv = 0.f, xhv = 0.f;
        {
            const size_t xoff = xbase + (size_t)t * Hh;
            if (tid < 256) { xzv = g_xz[xoff]; xhv = g_xh[xoff]; }
            else           { xrv = g_xr[xoff]; }
        }

        float2 v[8];
#pragma unroll
        for (int j = 0; j < 8; j++) v[j] = make_float2(0.f, 0.f);
#pragma unroll
        for (int kk = 0; kk < 16; kk++) {
            float4 h4 = *reinterpret_cast<const float4*>(&sm[p1hb + kk * 4]);
            float2 u01 = make_float2(Ug[kk].x, Ug[kk].y);
            float2 u23 = make_float2(Ug[kk].z, Ug[kk].w);
            const float hb[4] = {h4.x, h4.y, h4.z, h4.w};
#pragma unroll
            for (int b = 0; b < 4; b++) {
                float2 h2 = make_float2(hb[b], hb[b]);
                v[2 * b]     = ffma2(u01, h2, v[2 * b]);
                v[2 * b + 1] = ffma2(u23, h2, v[2 * b + 1]);
            }
        }
        {
            const bool hi2 = (p1k >> 1) & 1;
#pragma unroll
            for (int j = 0; j < 4; j++) {
                float sx = hi2 ? v[j].x : v[j + 4].x;
                float sy = hi2 ? v[j].y : v[j + 4].y;
                float rx = __shfl_xor_sync(0xffffffffu, sx, 2);
                float ry = __shfl_xor_sync(0xffffffffu, sy, 2);
                if (hi2) { v[j + 4].x += rx; v[j + 4].y += ry; }
                else     { v[j].x     += rx; v[j].y     += ry; }
            }
            float2 w[4];
#pragma unroll
            for (int j = 0; j < 4; j++) {
                w[j].x = hi2 ? v[j + 4].x : v[j].x;
                w[j].y = hi2 ? v[j + 4].y : v[j].y;
            }
            const bool hi1 = p1k & 1;
#pragma unroll
            for (int j = 0; j < 2; j++) {
                float sx = hi1 ? w[j].x : w[j + 2].x;
                float sy = hi1 ? w[j].y : w[j + 2].y;
                float rx = __shfl_xor_sync(0xffffffffu, sx, 1);
                float ry = __shfl_xor_sync(0xffffffffu, sy, 1);
                if (hi1) { w[j + 2].x += rx; w[j + 2].y += ry; }
                else     { w[j].x     += rx; w[j].y     += ry; }
            }
            float2 f0, f1;
            f0.x = hi1 ? w[2].x : w[0].x;  f0.y = hi1 ? w[2].y : w[0].y;
            f1.x = hi1 ? w[3].x : w[1].x;  f1.y = hi1 ? w[3].y : w[1].y;
            uint32_t addr = inzr_base +
                (uint32_t)((((rank * 2 + gate) * 4 + p1k) * 64 + p1cl) * 4);
            st_remote_f4(addr, p1dst, make_float4(f0.x, f0.y, f1.x, f1.y));
        }
        __syncwarp();
        if ((tid & 31) == 0) mbar_arrive_remote(mbzr, p1dst);

        mbar_wait_parity(mbzr, ph);
        if (tid < 256) {
            float sz = xzv;
#pragma unroll
            for (int s = 0; s < 4; s++)
                sz += sm[INZR_OFF + ((s * 2 + 0) * 4 + rb) * 64 + rcl];
            zkeep = hsig(sz);
        } else {
            float sr = xrv;
#pragma unroll
            for (int s = 0; s < 4; s++)
                sr += sm[INZR_OFF + ((s * 2 + 1) * 4 + rb) * 64 + rcl];
            const float r = hsig(sr);
            const float hprev = sm[HT_OFF + rswz + rb];
            sm[RHT_OFF + rswz + rb] = r * hprev;
        }
        __syncthreads();

#pragma unroll
        for (int j = 0; j < 8; j++) v[j] = make_float2(0.f, 0.f);
#pragma unroll
        for (int kk = 0; kk < 8; kk++) {
            const int krow = (p2k * 8 + kk) * 256 + p2crot;
            float4 uh = *reinterpret_cast<const float4*>(&sm[UH_OFF + krow]);
            float4 r4 = *reinterpret_cast<const float4*>(&sm[p2hb + kk * 4]);
            float2 u01 = make_float2(uh.x, uh.y);
            float2 u23 = make_float2(uh.z, uh.w);
            const float rv[4] = {r4.x, r4.y, r4.z, r4.w};
#pragma unroll
            for (int b = 0; b < 4; b++) {
                float2 r2 = make_float2(rv[b], rv[b]);
                v[2 * b]     = ffma2(u01, r2, v[2 * b]);
                v[2 * b + 1] = ffma2(u23, r2, v[2 * b + 1]);
            }
        }
        {
            const bool h4b = (p2k >> 2) & 1;
#pragma unroll
            for (int j = 0; j < 4; j++) {
                float sx = h4b ? v[j].x : v[j + 4].x;
                float sy = h4b ? v[j].y : v[j + 4].y;
                float rx = __shfl_xor_sync(0xffffffffu, sx, 4);
                float ry = __shfl_xor_sync(0xffffffffu, sy, 4);
                if (h4b) { v[j + 4].x += rx; v[j + 4].y += ry; }
                else     { v[j].x     += rx; v[j].y     += ry; }
            }
            float2 w[4];
#pragma unroll
            for (int j = 0; j < 4; j++) {
                w[j].x = h4b ? v[j + 4].x : v[j].x;
                w[j].y = h4b ? v[j + 4].y : v[j].y;
            }
            const bool h2b = (p2k >> 1) & 1;
#pragma unroll
            for (int j = 0; j < 2; j++) {
                float sx = h2b ? w[j].x : w[j + 2].x;
                float sy = h2b ? w[j].y : w[j + 2].y;
                float rx = __shfl_xor_sync(0xffffffffu, sx, 2);
                float ry = __shfl_xor_sync(0xffffffffu, sy, 2);
                if (h2b) { w[j + 2].x += rx; w[j + 2].y += ry; }
                else     { w[j].x     += rx; w[j].y     += ry; }
            }
            float2 u0, u1;
            u0.x = h2b ? w[2].x : w[0].x;  u0.y = h2b ? w[2].y : w[0].y;
            u1.x = h2b ? w[3].x : w[1].x;  u1.y = h2b ? w[3].y : w[1].y;
            const bool h1b = p2k & 1;
            {
                float sx = h1b ? u0.x : u1.x;
                float sy = h1b ? u0.y : u1.y;
                float rx = __shfl_xor_sync(0xffffffffu, sx, 1);
                float ry = __shfl_xor_sync(0xffffffffu, sy, 1);
                if (h1b) { u1.x += rx; u1.y += ry; }
                else     { u0.x += rx; u0.y += ry; }
            }
            float2 fin;
            fin.x = h1b ? u1.x : u0.x;
            fin.y = h1b ? u1.y : u0.y;
            uint32_t addr = inh_base +
                (uint32_t)(((rank * 4 + (p2k >> 1)) * 64 + p2cl + (p2k & 1) * 2) * 4);
            st_remote_f2(addr, p2dst, fin);
        }
        __syncwarp();
        if ((tid & 31) == 0) mbar_arrive_remote(mbh, p2dst);

        if (tid < 256) {
            mbar_wait_parity(mbh, ph);
            float sh = xhv;
#pragma unroll
            for (int s = 0; s < 4; s++)
                sh += sm[INH_OFF + (s * 4 + rb) * 64 + rcl];
            const float hh = tanhf(sh);
            h_reg = zkeep * h_reg + (1.0f - zkeep) * hh;
            sm[HT_OFF + rswz + rb] = h_reg;
        }
        __syncthreads();
    }

    if (tid < 256)
        out[(size_t)bglob * Hh + cglob] = h_reg;

    cluster_sync_();
}

extern "C" void kernel_launch(void* const* d_in, const int* in_sizes, int n_in,
                              void* d_out, int out_size) {
    (void)in_sizes; (void)n_in; (void)out_size;
    const float* x  = (const float*)d_in[0];
    const float* Wz = (const float*)d_in[1];
    const float* Wr = (const float*)d_in[2];
    const float* Wh = (const float*)d_in[3];
    const float* Uz = (const float*)d_in[4];
    const float* Ur = (const float*)d_in[5];
    const float* Uh = (const float*)d_in[6];
    const float* bz = (const float*)d_in[7];
    const float* br = (const float*)d_in[8];
    const float* bh = (const float*)d_in[9];
    float* out = (float*)d_out;

    static int smem_set = 0;
    if (!smem_set) {
        cudaFuncSetAttribute(scan_cluster_kernel,
                             cudaFuncAttributeMaxDynamicSharedMemorySize,
                             SMEM_FLOATS * sizeof(float));
        cudaFuncSetAttribute(proj_mma_kernel,
                             cudaFuncAttributeMaxDynamicSharedMemorySize,
                             PROJ_SMEM_BYTES);
        smem_set = 1;
    }

    proj_mma_kernel<<<BT / 128, 256, PROJ_SMEM_BYTES>>>(x, Wz, Wr, Wh, bz, br, bh);
    scan_cluster_kernel<<<Bb, 512, SMEM_FLOATS * sizeof(float)>>>(Uz, Ur, Uh, out);
}